// round 9
// baseline (speedup 1.0000x reference)
#include <cuda_runtime.h>
#include <cuda_bf16.h>
#include <cstdint>

#define BDIM 2
#define NDIM 1000
#define EDIM 2000
#define HDIM 128
#define RTOT (BDIM * EDIM)          // 4000 flat rows

#define HSPLIT 4                    // h-splits for econv tensor kernel
#define NH_PER (HDIM / HSPLIT)      // 32 h per block

#define ZN2E 4                      // split-K for n2e tc-gemm (K=1000 -> 250)
#define ZAGG 8                      // split-K for agg tc-gemm (K=2000 -> 250)
#define KCH2 250

// ---------------- scratch (device globals) ---------------------------------
__device__ float g_embp[(size_t)ZN2E * RTOT * HDIM];          // n2e partials
__device__ float g_newp[(size_t)HSPLIT * RTOT * HDIM];        // econv partials
__device__ float g_newT[(size_t)BDIM * HDIM * EDIM];          // new_n2e^T [b][i][e]
__device__ float g_aggp[(size_t)ZAGG * BDIM * NDIM * HDIM];   // agg partials
__device__ float g_inv [(size_t)BDIM * NDIM];
__device__ float g_nsT [(size_t)BDIM * HDIM * NDIM];          // node_state^T
// pre-split EN (bf16 hi/lo planes), plain [h][i][j] layout
__device__ unsigned short g_ENhi[(size_t)HDIM * 16384];
__device__ unsigned short g_ENlo[(size_t)HDIM * 16384];

// ---------------- mma.sync / cp.async helpers --------------------------------
__device__ __forceinline__ uint32_t smem_u32(const void* p) {
    uint32_t a;
    asm("{ .reg .u64 t; cvta.to.shared.u64 t, %1; cvt.u32.u64 %0, t; }"
        : "=r"(a) : "l"(p));
    return a;
}
__device__ __forceinline__ void ldsm4(uint32_t* r, uint32_t addr) {
    asm volatile("ldmatrix.sync.aligned.m8n8.x4.shared.b16 {%0,%1,%2,%3}, [%4];"
                 : "=r"(r[0]), "=r"(r[1]), "=r"(r[2]), "=r"(r[3]) : "r"(addr));
}
__device__ __forceinline__ void mma_bf16(float* d, const uint32_t* a,
                                         uint32_t b0, uint32_t b1) {
    asm volatile("mma.sync.aligned.m16n8k16.row.col.f32.bf16.bf16.f32 "
                 "{%0,%1,%2,%3}, {%4,%5,%6,%7}, {%8,%9}, {%0,%1,%2,%3};"
                 : "+f"(d[0]), "+f"(d[1]), "+f"(d[2]), "+f"(d[3])
                 : "r"(a[0]), "r"(a[1]), "r"(a[2]), "r"(a[3]), "r"(b0), "r"(b1));
}
__device__ __forceinline__ uint32_t cvt2(float lo, float hi) {
    uint32_t r;
    asm("cvt.rn.satfinite.bf16x2.f32 %0, %1, %2;" : "=r"(r) : "f"(hi), "f"(lo));
    return r;
}
__device__ __forceinline__ void cp16(uint32_t dst, const void* src) {
    asm volatile("cp.async.cg.shared.global [%0], [%1], 16;"
                 :: "r"(dst), "l"(src) : "memory");
}
__device__ __forceinline__ void cp_commit() {
    asm volatile("cp.async.commit_group;" ::: "memory");
}
__device__ __forceinline__ void cp_wait0() {
    asm volatile("cp.async.wait_group 0;" ::: "memory");
}

// ---------------------------------------------------------------------------
// Tile transpose: in [b][R][C] -> out [b][C][R]
// ---------------------------------------------------------------------------
__global__ void __launch_bounds__(256) k_tr(const float* __restrict__ in,
                                            float* __restrict__ out,
                                            int R, int C) {
    __shared__ float tile[32][33];
    int b = blockIdx.z;
    const float* inb = in + (size_t)b * R * C;
    float* outb = out + (size_t)b * C * R;
    int rbase = blockIdx.x * 32, cbase = blockIdx.y * 32;
    for (int rr = threadIdx.y; rr < 32; rr += 8) {
        int r = rbase + rr, c = cbase + threadIdx.x;
        tile[rr][threadIdx.x] = (r < R && c < C) ? inb[(size_t)r * C + c] : 0.f;
    }
    __syncthreads();
    for (int cc = threadIdx.y; cc < 32; cc += 8) {
        int c = cbase + cc, r = rbase + threadIdx.x;
        if (c < C && r < R) outb[(size_t)c * R + r] = tile[threadIdx.x][cc];
    }
}

// ---------------------------------------------------------------------------
// Tensor-core split-K GEMM (3-term bf16 split):
//   out[z][b][r][i] = sum_{k in chunk z} A[b][r][k] * BT[b][i][k]
// M-tile 128 x N=128, K-chunk 250 (4 sub-tiles of 64, last 58 zero-padded).
// 512 threads, 16 warps, warp tile 32x32.
// ---------------------------------------------------------------------------
#define TSTR 144u                   // (64 bf16 = 128B) + 16B pad
#define OFF2_AH 0u
#define OFF2_AL 18432u              // 128*144
#define OFF2_BH 36864u
#define OFF2_BL 55296u
#define SM_GEMM2 73728u

__global__ void __launch_bounds__(512) k_gemm_tc(const float* __restrict__ A,
                                                 const float* __restrict__ BT,
                                                 float* __restrict__ out,
                                                 int ROWS, int KTOT) {
    extern __shared__ char smraw[];
    uint32_t base32 = smem_u32(smraw);

    int t = threadIdx.x;
    int lane = t & 31, w = t >> 5;
    int b  = blockIdx.y;
    int z  = blockIdx.z;
    int r0 = blockIdx.x * 128;

    const float* Ab  = A  + (size_t)b * ROWS * KTOT;
    const float* BTb = BT + (size_t)b * HDIM * KTOT;

    float acc[2][4][4];
#pragma unroll
    for (int ms = 0; ms < 2; ms++)
#pragma unroll
        for (int nt = 0; nt < 4; nt++)
#pragma unroll
            for (int q = 0; q < 4; q++) acc[ms][nt][q] = 0.f;

    int warpM = (w & 3) * 32;
    int warpN = (w >> 2) * 32;
    uint32_t aoff = (uint32_t)(warpM + (lane & 15)) * TSTR + (uint32_t)(lane >> 4) * 16u;
    uint32_t boff = (uint32_t)(warpN + ((lane >> 4) & 1) * 8 + (lane & 7)) * TSTR
                  + (uint32_t)((lane >> 3) & 1) * 16u;
    uint32_t AbH = base32 + OFF2_AH + aoff;
    uint32_t AbL = base32 + OFF2_AL + aoff;
    uint32_t BbH = base32 + OFF2_BH + boff;
    uint32_t BbL = base32 + OFF2_BL + boff;

    for (int kc = 0; kc < 4; kc++) {
        int k0 = z * KCH2 + kc * 64;
        int kw = KCH2 - kc * 64; if (kw > 64) kw = 64;   // 64,64,64,58
        __syncthreads();
        // ---- load + split A tile [128][64] ----
#pragma unroll
        for (int q = 0; q < 8; q++) {
            int p = t + 512 * q;               // pair index 0..4095
            int m = p >> 5, jp = p & 31;
            int r = r0 + m;
            float x = 0.f, y = 0.f;
            if (r < ROWS) {
                const float* ar = Ab + (size_t)r * KTOT + k0;
                if (jp * 2 < kw)     x = ar[jp * 2];
                if (jp * 2 + 1 < kw) y = ar[jp * 2 + 1];
            }
            uint32_t hp = cvt2(x, y);
            float h0 = __uint_as_float(hp << 16);
            float h1 = __uint_as_float(hp & 0xFFFF0000u);
            uint32_t lp = cvt2(x - h0, y - h1);
            *(uint32_t*)(smraw + OFF2_AH + (uint32_t)m * TSTR + jp * 4) = hp;
            *(uint32_t*)(smraw + OFF2_AL + (uint32_t)m * TSTR + jp * 4) = lp;
        }
        // ---- load + split B tile [128][64] (BT rows = i) ----
#pragma unroll
        for (int q = 0; q < 8; q++) {
            int p = t + 512 * q;
            int i = p >> 5, jp = p & 31;
            const float* br = BTb + (size_t)i * KTOT + k0;
            float x = 0.f, y = 0.f;
            if (jp * 2 < kw)     x = br[jp * 2];
            if (jp * 2 + 1 < kw) y = br[jp * 2 + 1];
            uint32_t hp = cvt2(x, y);
            float h0 = __uint_as_float(hp << 16);
            float h1 = __uint_as_float(hp & 0xFFFF0000u);
            uint32_t lp = cvt2(x - h0, y - h1);
            *(uint32_t*)(smraw + OFF2_BH + (uint32_t)i * TSTR + jp * 4) = hp;
            *(uint32_t*)(smraw + OFF2_BL + (uint32_t)i * TSTR + jp * 4) = lp;
        }
        __syncthreads();

#pragma unroll
        for (int ks = 0; ks < 4; ks++) {
            uint32_t ah0[4], ah1[4], al0[4], al1[4];
            ldsm4(ah0, AbH + ks * 32u);
            ldsm4(ah1, AbH + 2304u + ks * 32u);      // +16 rows
            ldsm4(al0, AbL + ks * 32u);
            ldsm4(al1, AbL + 2304u + ks * 32u);
            uint32_t bh[2][4], bl[2][4];
#pragma unroll
            for (int np = 0; np < 2; np++) {
                ldsm4(bh[np], BbH + (uint32_t)np * 2304u + ks * 32u);
                ldsm4(bl[np], BbL + (uint32_t)np * 2304u + ks * 32u);
            }
#pragma unroll
            for (int nt = 0; nt < 4; nt++) {
                uint32_t b0h = bh[nt >> 1][(nt & 1) * 2];
                uint32_t b1h = bh[nt >> 1][(nt & 1) * 2 + 1];
                uint32_t b0l = bl[nt >> 1][(nt & 1) * 2];
                uint32_t b1l = bl[nt >> 1][(nt & 1) * 2 + 1];
                mma_bf16(acc[0][nt], ah0, b0h, b1h);   // AH*BH
                mma_bf16(acc[1][nt], ah1, b0h, b1h);
                mma_bf16(acc[0][nt], ah0, b0l, b1l);   // AH*BL
                mma_bf16(acc[1][nt], ah1, b0l, b1l);
                mma_bf16(acc[0][nt], al0, b0h, b1h);   // AL*BH
                mma_bf16(acc[1][nt], al1, b0h, b1h);
            }
        }
    }

    // ---- epilogue: partial write [z][b][r][i] ----
#pragma unroll
    for (int ms = 0; ms < 2; ms++) {
        int rA = r0 + warpM + ms * 16 + (lane >> 2);
        int rB = rA + 8;
#pragma unroll
        for (int nt = 0; nt < 4; nt++) {
            int col = warpN + nt * 8 + (lane & 3) * 2;
            if (rA < ROWS)
                *(float2*)&out[((size_t)z * BDIM * ROWS + (size_t)b * ROWS + rA)
                               * HDIM + col] =
                    make_float2(acc[ms][nt][0], acc[ms][nt][1]);
            if (rB < ROWS)
                *(float2*)&out[((size_t)z * BDIM * ROWS + (size_t)b * ROWS + rB)
                               * HDIM + col] =
                    make_float2(acc[ms][nt][2], acc[ms][nt][3]);
        }
    }
}

// ---------------------------------------------------------------------------
// Prep: split EN into bf16 hi/lo planes, plain [h][i][j]
// ---------------------------------------------------------------------------
__global__ void __launch_bounds__(256) k_prep(const float* __restrict__ EN) {
    int h = blockIdx.x;
    int t = threadIdx.x;
    const float* src = EN + (size_t)h * 16384;
    unsigned short* dh = g_ENhi + (size_t)h * 16384;
    unsigned short* dl = g_ENlo + (size_t)h * 16384;
    for (int idx = t; idx < 16384; idx += 256) {
        float v = src[idx];
        __nv_bfloat16 hb = __float2bfloat16(v);
        float hf = __bfloat162float(hb);
        __nv_bfloat16 lb = __float2bfloat16(v - hf);
        dh[idx] = *(unsigned short*)&hb;
        dl[idx] = *(unsigned short*)&lb;
    }
}

// ---------------------------------------------------------------------------
// Tensor-core econv: A fragments REGISTER-RESIDENT across the h loop
// (A = emb hi/lo is h-invariant). B (EN planes) double-buffered via cp.async.
// A-build sums the ZN2E split-K partials directly (k_red fused away).
// 512 threads = 16 warps; warp tile 32x32.
// ---------------------------------------------------------------------------
#define ASTRB 272u
#define PLANE 34816u
#define OFF_AH 0u
#define OFF_AL 34816u
#define OFF_B  69632u
#define OFF_EV 208896u
#define SM_ECONV 225280u

__global__ void __launch_bounds__(512) k_econv_tc(const float* __restrict__ ev,
                                                  const unsigned short* __restrict__ ENhi,
                                                  const unsigned short* __restrict__ ENlo,
                                                  float* __restrict__ newp) {
    extern __shared__ char smraw[];
    uint32_t base32 = smem_u32(smraw);
    float* evs = (float*)(smraw + OFF_EV);

    int t = threadIdx.x;
    int lane = t & 31, w = t >> 5;
    int r0 = blockIdx.x * 128;
    int hbase = blockIdx.y * NH_PER;

    // ---- issue stage-0 B copy immediately (overlaps A build) ----
    {
        const char* sH = (const char*)(ENhi + (size_t)hbase * 16384);
        const char* sL = (const char*)(ENlo + (size_t)hbase * 16384);
        uint32_t dst = base32 + OFF_B;
#pragma unroll
        for (int k = 0; k < 4; k++) {
            int f = t + 512 * k;
            uint32_t i = (uint32_t)(f >> 4), seg = (uint32_t)(f & 15);
            uint32_t o = i * ASTRB + seg * 16u;
            cp16(dst + o,          sH + (size_t)f * 16);
            cp16(dst + PLANE + o,  sL + (size_t)f * 16);
        }
        cp_commit();
    }

    // ---- build A planes: emb = sum_z embp[z], split hi/lo bf16 ----
#pragma unroll 4
    for (int k = 0; k < 16; k++) {
        int p = t + 512 * k;
        int m = p >> 6, jp = p & 63;
        int r = r0 + m;
        float ex = 0.f, ey = 0.f;
        if (r < RTOT) {
#pragma unroll
            for (int z = 0; z < ZN2E; z++) {
                float2 v = *(const float2*)&g_embp[((size_t)z * RTOT + r) * HDIM
                                                   + jp * 2];
                ex += v.x; ey += v.y;
            }
        }
        uint32_t hp = cvt2(ex, ey);
        float h0 = __uint_as_float(hp << 16);
        float h1 = __uint_as_float(hp & 0xFFFF0000u);
        uint32_t lp = cvt2(ex - h0, ey - h1);
        *(uint32_t*)(smraw + OFF_AH + (uint32_t)m * ASTRB + jp * 4) = hp;
        *(uint32_t*)(smraw + OFF_AL + (uint32_t)m * ASTRB + jp * 4) = lp;
    }
    // ---- stage ev slice ----
    for (int idx = t; idx < NH_PER * 128; idx += 512) {
        int hh = idx >> 7, m = idx & 127;
        int r = r0 + m;
        evs[hh * 128 + m] = (r < RTOT) ? ev[(size_t)r * HDIM + hbase + hh] : 0.f;
    }
    __syncthreads();                 // A planes + evs visible

    int warpM = (w & 3) * 32;
    int warpN = (w >> 2) * 32;
    uint32_t aoff = (uint32_t)(warpM + (lane & 15)) * ASTRB + (uint32_t)(lane >> 4) * 16u;
    uint32_t boff = (uint32_t)(warpN + ((lane >> 4) & 1) * 8 + (lane & 7)) * ASTRB
                  + (uint32_t)((lane >> 3) & 1) * 16u;
    uint32_t AbH = base32 + OFF_AH + aoff;
    uint32_t AbL = base32 + OFF_AL + aoff;

    // ---- hoist A fragments into registers (h-invariant) ----
    uint32_t ah0f[8][4], ah1f[8][4], al0f[8][4], al1f[8][4];
#pragma unroll
    for (int ks = 0; ks < 8; ks++) {
        ldsm4(ah0f[ks], AbH + ks * 32u);
        ldsm4(ah1f[ks], AbH + 4352u + ks * 32u);
        ldsm4(al0f[ks], AbL + ks * 32u);
        ldsm4(al1f[ks], AbL + 4352u + ks * 32u);
    }

    float acc[2][4][4];
#pragma unroll
    for (int ms = 0; ms < 2; ms++)
#pragma unroll
        for (int nt = 0; nt < 4; nt++)
#pragma unroll
            for (int q = 0; q < 4; q++) acc[ms][nt][q] = 0.f;

    int rl0 = warpM + (lane >> 2);

    for (int hh = 0; hh < NH_PER; hh++) {
        int s = hh & 1;
        cp_wait0();
        __syncthreads();

        if (hh + 1 < NH_PER) {
            const char* sH = (const char*)(ENhi + (size_t)(hbase + hh + 1) * 16384);
            const char* sL = (const char*)(ENlo + (size_t)(hbase + hh + 1) * 16384);
            uint32_t dst = base32 + OFF_B + (uint32_t)(1 - s) * 69632u;
#pragma unroll
            for (int k = 0; k < 4; k++) {
                int f = t + 512 * k;
                uint32_t i = (uint32_t)(f >> 4), seg = (uint32_t)(f & 15);
                uint32_t o = i * ASTRB + seg * 16u;
                cp16(dst + o,         sH + (size_t)f * 16);
                cp16(dst + PLANE + o, sL + (size_t)f * 16);
            }
            cp_commit();
        }

        uint32_t BbH = base32 + OFF_B + (uint32_t)s * 69632u + boff;
        uint32_t BbL = BbH + PLANE;

        float tt[2][4][4];
#pragma unroll
        for (int ms = 0; ms < 2; ms++)
#pragma unroll
            for (int nt = 0; nt < 4; nt++)
#pragma unroll
                for (int q = 0; q < 4; q++) tt[ms][nt][q] = 0.f;

#pragma unroll
        for (int ks = 0; ks < 8; ks++) {
            uint32_t bh[2][4], bl[2][4];
#pragma unroll
            for (int np = 0; np < 2; np++) {
                ldsm4(bh[np], BbH + (uint32_t)np * 4352u + ks * 32u);
                ldsm4(bl[np], BbL + (uint32_t)np * 4352u + ks * 32u);
            }
#pragma unroll
            for (int nt = 0; nt < 4; nt++) {
                uint32_t b0h = bh[nt >> 1][(nt & 1) * 2];
                uint32_t b1h = bh[nt >> 1][(nt & 1) * 2 + 1];
                uint32_t b0l = bl[nt >> 1][(nt & 1) * 2];
                uint32_t b1l = bl[nt >> 1][(nt & 1) * 2 + 1];
                mma_bf16(tt[0][nt], ah0f[ks], b0h, b1h);   // AH*BH
                mma_bf16(tt[1][nt], ah1f[ks], b0h, b1h);
                mma_bf16(tt[0][nt], ah0f[ks], b0l, b1l);   // AH*BL
                mma_bf16(tt[1][nt], ah1f[ks], b0l, b1l);
                mma_bf16(tt[0][nt], al0f[ks], b0h, b1h);   // AL*BH
                mma_bf16(tt[1][nt], al1f[ks], b0h, b1h);
            }
        }

        const float* evh = evs + hh * 128;
        float ev0A = evh[rl0];
        float ev0B = evh[rl0 + 8];
        float ev1A = evh[rl0 + 16];
        float ev1B = evh[rl0 + 24];
#pragma unroll
        for (int nt = 0; nt < 4; nt++) {
            acc[0][nt][0] += ev0A * tt[0][nt][0];
            acc[0][nt][1] += ev0A * tt[0][nt][1];
            acc[0][nt][2] += ev0B * tt[0][nt][2];
            acc[0][nt][3] += ev0B * tt[0][nt][3];
            acc[1][nt][0] += ev1A * tt[1][nt][0];
            acc[1][nt][1] += ev1A * tt[1][nt][1];
            acc[1][nt][2] += ev1B * tt[1][nt][2];
            acc[1][nt][3] += ev1B * tt[1][nt][3];
        }
    }

    size_t obase = (size_t)blockIdx.y * RTOT * HDIM;
#pragma unroll
    for (int ms = 0; ms < 2; ms++) {
        int rA = r0 + warpM + ms * 16 + (lane >> 2);
        int rB = rA + 8;
#pragma unroll
        for (int nt = 0; nt < 4; nt++) {
            int col = warpN + nt * 8 + (lane & 3) * 2;
            if (rA < RTOT)
                *(float2*)&newp[obase + (size_t)rA * HDIM + col] =
                    make_float2(acc[ms][nt][0], acc[ms][nt][1]);
            if (rB < RTOT)
                *(float2*)&newp[obase + (size_t)rB * HDIM + col] =
                    make_float2(acc[ms][nt][2], acc[ms][nt][3]);
        }
    }
}

// ---------------------------------------------------------------------------
// Fused HSPLIT-reduce + transpose: g_newT[b][i][e] = sum_hs newp[hs][b*E+e][i]
// Tiled 32x32, coalesced read and write. grid (63, 4, BDIM), 256 thr.
// ---------------------------------------------------------------------------
__global__ void __launch_bounds__(256) k_nredT(const float* __restrict__ newp) {
    __shared__ float tile[32][33];
    int b  = blockIdx.z;
    int e0 = blockIdx.x * 32, i0 = blockIdx.y * 32;
    int tx = threadIdx.x & 31, ty = threadIdx.x >> 5;

    for (int rr = ty; rr < 32; rr += 8) {
        int e = e0 + rr;
        float s = 0.f;
        if (e < EDIM) {
            size_t base = ((size_t)b * EDIM + e) * HDIM + i0 + tx;
#pragma unroll
            for (int z = 0; z < HSPLIT; z++)
                s += newp[(size_t)z * RTOT * HDIM + base];
        }
        tile[rr][tx] = s;
    }
    __syncthreads();
    for (int cc = ty; cc < 32; cc += 8) {
        int i = i0 + cc;
        int e = e0 + tx;
        if (e < EDIM)
            g_newT[((size_t)b * HDIM + i) * EDIM + e] = tile[tx][cc];
    }
}

__global__ void __launch_bounds__(256) k_norm(const float* __restrict__ e2n) {
    __shared__ float red[256];
    int row = blockIdx.x;
    const float* p = e2n + (size_t)row * EDIM;
    float s = 0.f;
    for (int e = threadIdx.x; e < EDIM; e += 256) s += p[e];
    red[threadIdx.x] = s;
    __syncthreads();
    for (int o = 128; o > 0; o >>= 1) {
        if (threadIdx.x < o) red[threadIdx.x] += red[threadIdx.x + o];
        __syncthreads();
    }
    if (threadIdx.x == 0) g_inv[row] = 1.f / (1.f + red[0]);
}

// out = (sum_z g_aggp[z] + node_state) * g_inv    (grid 250 exact)
__global__ void __launch_bounds__(256) k_fin(const float* __restrict__ ns,
                                             float* __restrict__ out) {
    const size_t STR = (size_t)BDIM * NDIM * HDIM / 4;
    size_t f = (size_t)blockIdx.x * 256 + threadIdx.x;
    const float4* p = (const float4*)g_aggp;
    float4 s = p[f];
#pragma unroll
    for (int z = 1; z < ZAGG; z++) {
        float4 v = p[z * STR + f];
        s.x += v.x; s.y += v.y; s.z += v.z; s.w += v.w;
    }
    float4 n4 = ((const float4*)ns)[f];
    float inv = g_inv[(f * 4) >> 7];
    float4 o;
    o.x = (s.x + n4.x) * inv;
    o.y = (s.y + n4.y) * inv;
    o.z = (s.z + n4.z) * inv;
    o.w = (s.w + n4.w) * inv;
    ((float4*)out)[f] = o;
}

// ---------------------------------------------------------------------------
extern "C" void kernel_launch(void* const* d_in, const int* in_sizes, int n_in,
                              void* d_out, int out_size) {
    const float* node_state   = (const float*)d_in[0];
    const float* edge_vec     = (const float*)d_in[1];
    const float* node2edge    = (const float*)d_in[2];
    const float* edge2node    = (const float*)d_in[3];
    const float* edge_network = (const float*)d_in[4];
    float* out = (float*)d_out;

    void* p_embp; cudaGetSymbolAddress(&p_embp, g_embp);
    void* p_newp; cudaGetSymbolAddress(&p_newp, g_newp);
    void* p_newT; cudaGetSymbolAddress(&p_newT, g_newT);
    void* p_aggp; cudaGetSymbolAddress(&p_aggp, g_aggp);
    void* p_nsT;  cudaGetSymbolAddress(&p_nsT,  g_nsT);
    void* p_enh;  cudaGetSymbolAddress(&p_enh,  g_ENhi);
    void* p_enl;  cudaGetSymbolAddress(&p_enl,  g_ENlo);

    cudaFuncSetAttribute(k_econv_tc, cudaFuncAttributeMaxDynamicSharedMemorySize,
                         SM_ECONV);
    cudaFuncSetAttribute(k_gemm_tc, cudaFuncAttributeMaxDynamicSharedMemorySize,
                         SM_GEMM2);

    // node_state^T: [b][1000][128] -> [b][128][1000]
    k_tr<<<dim3(32, 4, BDIM), dim3(32, 8)>>>(node_state, (float*)p_nsT,
                                             NDIM, HDIM);
    k_prep<<<HDIM, 256>>>(edge_network);
    // n2e: A=node2edge [b][E][N], BT=nsT -> partials (16,2,4)=128 blocks
    k_gemm_tc<<<dim3(16, BDIM, ZN2E), 512, SM_GEMM2>>>(node2edge,
                                                       (const float*)p_nsT,
                                                       (float*)p_embp,
                                                       EDIM, NDIM);
    // econv (A-build fuses the split-K reduce of g_embp)
    k_econv_tc<<<dim3(32, HSPLIT), 512, SM_ECONV>>>(edge_vec,
                                                    (const unsigned short*)p_enh,
                                                    (const unsigned short*)p_enl,
                                                    (float*)p_newp);
    // HSPLIT-reduce + transpose -> g_newT
    k_nredT<<<dim3(63, 4, BDIM), 256>>>((const float*)p_newp);
    // agg: A=edge2node [b][N][E], BT=g_newT -> partials (8,2,8)=128 blocks
    k_gemm_tc<<<dim3(8, BDIM, ZAGG), 512, SM_GEMM2>>>(edge2node,
                                                      (const float*)p_newT,
                                                      (float*)p_aggp,
                                                      NDIM, EDIM);
    k_norm<<<BDIM * NDIM, 256>>>(edge2node);
    k_fin<<<250, 256>>>(node_state, out);
}

// round 10
// speedup vs baseline: 1.3054x; 1.3054x over previous
#include <cuda_runtime.h>
#include <cuda_bf16.h>
#include <cstdint>

#define BDIM 2
#define NDIM 1000
#define EDIM 2000
#define HDIM 128
#define RTOT (BDIM * EDIM)          // 4000 flat rows

#define HSPLIT 4                    // h-splits for econv tensor kernel
#define NH_PER (HDIM / HSPLIT)      // 32 h per block

#define ZN2E 4                      // split-K for n2e tc-gemm (K=1000 -> 250)
#define ZAGG 8                      // split-K for agg tc-gemm (K=2000 -> 250)
#define KCH2 250

// ---------------- scratch (device globals) ---------------------------------
__device__ float g_embp[(size_t)ZN2E * RTOT * HDIM];          // n2e partials
__device__ float g_newp[(size_t)HSPLIT * RTOT * HDIM];        // econv partials
__device__ float g_newT[(size_t)BDIM * HDIM * EDIM];          // new_n2e^T [b][i][e]
__device__ float g_aggp[(size_t)ZAGG * BDIM * NDIM * HDIM];   // agg partials
__device__ float g_inv [(size_t)BDIM * NDIM];
__device__ float g_nsT [(size_t)BDIM * HDIM * NDIM];          // node_state^T
// pre-split EN (bf16 hi/lo planes), plain [h][i][j] layout
__device__ unsigned short g_ENhi[(size_t)HDIM * 16384];
__device__ unsigned short g_ENlo[(size_t)HDIM * 16384];

// ---------------- mma.sync / cp.async helpers --------------------------------
__device__ __forceinline__ uint32_t smem_u32(const void* p) {
    uint32_t a;
    asm("{ .reg .u64 t; cvta.to.shared.u64 t, %1; cvt.u32.u64 %0, t; }"
        : "=r"(a) : "l"(p));
    return a;
}
__device__ __forceinline__ void ldsm4(uint32_t* r, uint32_t addr) {
    asm volatile("ldmatrix.sync.aligned.m8n8.x4.shared.b16 {%0,%1,%2,%3}, [%4];"
                 : "=r"(r[0]), "=r"(r[1]), "=r"(r[2]), "=r"(r[3]) : "r"(addr));
}
__device__ __forceinline__ void mma_bf16(float* d, const uint32_t* a,
                                         uint32_t b0, uint32_t b1) {
    asm volatile("mma.sync.aligned.m16n8k16.row.col.f32.bf16.bf16.f32 "
                 "{%0,%1,%2,%3}, {%4,%5,%6,%7}, {%8,%9}, {%0,%1,%2,%3};"
                 : "+f"(d[0]), "+f"(d[1]), "+f"(d[2]), "+f"(d[3])
                 : "r"(a[0]), "r"(a[1]), "r"(a[2]), "r"(a[3]), "r"(b0), "r"(b1));
}
__device__ __forceinline__ uint32_t cvt2(float lo, float hi) {
    uint32_t r;
    asm("cvt.rn.satfinite.bf16x2.f32 %0, %1, %2;" : "=r"(r) : "f"(hi), "f"(lo));
    return r;
}
__device__ __forceinline__ void cp16(uint32_t dst, const void* src) {
    asm volatile("cp.async.cg.shared.global [%0], [%1], 16;"
                 :: "r"(dst), "l"(src) : "memory");
}
__device__ __forceinline__ void cp_commit() {
    asm volatile("cp.async.commit_group;" ::: "memory");
}
__device__ __forceinline__ void cp_wait0() {
    asm volatile("cp.async.wait_group 0;" ::: "memory");
}

// ---------------------------------------------------------------------------
// Tile transpose: in [b][R][C] -> out [b][C][R]
// ---------------------------------------------------------------------------
__global__ void __launch_bounds__(256) k_tr(const float* __restrict__ in,
                                            float* __restrict__ out,
                                            int R, int C) {
    __shared__ float tile[32][33];
    int b = blockIdx.z;
    const float* inb = in + (size_t)b * R * C;
    float* outb = out + (size_t)b * C * R;
    int rbase = blockIdx.x * 32, cbase = blockIdx.y * 32;
    for (int rr = threadIdx.y; rr < 32; rr += 8) {
        int r = rbase + rr, c = cbase + threadIdx.x;
        tile[rr][threadIdx.x] = (r < R && c < C) ? inb[(size_t)r * C + c] : 0.f;
    }
    __syncthreads();
    for (int cc = threadIdx.y; cc < 32; cc += 8) {
        int c = cbase + cc, r = rbase + threadIdx.x;
        if (c < C && r < R) outb[(size_t)c * R + r] = tile[threadIdx.x][cc];
    }
}

// ---------------------------------------------------------------------------
// Tensor-core split-K GEMM (3-term bf16 split):
//   out[z][b][r][i] = sum_{k in chunk z} A[b][r][k] * BT[b][i][k]
// M-tile 128 x N=128, K-chunk 250 (4 sub-tiles of 64, last 58 zero-padded).
// 512 threads, 16 warps, warp tile 32x32.
// ---------------------------------------------------------------------------
#define TSTR 144u                   // (64 bf16 = 128B) + 16B pad
#define OFF2_AH 0u
#define OFF2_AL 18432u              // 128*144
#define OFF2_BH 36864u
#define OFF2_BL 55296u
#define SM_GEMM2 73728u

__global__ void __launch_bounds__(512) k_gemm_tc(const float* __restrict__ A,
                                                 const float* __restrict__ BT,
                                                 float* __restrict__ out,
                                                 int ROWS, int KTOT) {
    extern __shared__ char smraw[];
    uint32_t base32 = smem_u32(smraw);

    int t = threadIdx.x;
    int lane = t & 31, w = t >> 5;
    int b  = blockIdx.y;
    int z  = blockIdx.z;
    int r0 = blockIdx.x * 128;

    const float* Ab  = A  + (size_t)b * ROWS * KTOT;
    const float* BTb = BT + (size_t)b * HDIM * KTOT;

    float acc[2][4][4];
#pragma unroll
    for (int ms = 0; ms < 2; ms++)
#pragma unroll
        for (int nt = 0; nt < 4; nt++)
#pragma unroll
            for (int q = 0; q < 4; q++) acc[ms][nt][q] = 0.f;

    int warpM = (w & 3) * 32;
    int warpN = (w >> 2) * 32;
    uint32_t aoff = (uint32_t)(warpM + (lane & 15)) * TSTR + (uint32_t)(lane >> 4) * 16u;
    uint32_t boff = (uint32_t)(warpN + ((lane >> 4) & 1) * 8 + (lane & 7)) * TSTR
                  + (uint32_t)((lane >> 3) & 1) * 16u;
    uint32_t AbH = base32 + OFF2_AH + aoff;
    uint32_t AbL = base32 + OFF2_AL + aoff;
    uint32_t BbH = base32 + OFF2_BH + boff;
    uint32_t BbL = base32 + OFF2_BL + boff;

    for (int kc = 0; kc < 4; kc++) {
        int k0 = z * KCH2 + kc * 64;
        int kw = KCH2 - kc * 64; if (kw > 64) kw = 64;   // 64,64,64,58
        __syncthreads();
        // ---- load + split A tile [128][64] ----
#pragma unroll
        for (int q = 0; q < 8; q++) {
            int p = t + 512 * q;               // pair index 0..4095
            int m = p >> 5, jp = p & 31;
            int r = r0 + m;
            float x = 0.f, y = 0.f;
            if (r < ROWS) {
                const float* ar = Ab + (size_t)r * KTOT + k0;
                if (jp * 2 < kw)     x = ar[jp * 2];
                if (jp * 2 + 1 < kw) y = ar[jp * 2 + 1];
            }
            uint32_t hp = cvt2(x, y);
            float h0 = __uint_as_float(hp << 16);
            float h1 = __uint_as_float(hp & 0xFFFF0000u);
            uint32_t lp = cvt2(x - h0, y - h1);
            *(uint32_t*)(smraw + OFF2_AH + (uint32_t)m * TSTR + jp * 4) = hp;
            *(uint32_t*)(smraw + OFF2_AL + (uint32_t)m * TSTR + jp * 4) = lp;
        }
        // ---- load + split B tile [128][64] (BT rows = i) ----
#pragma unroll
        for (int q = 0; q < 8; q++) {
            int p = t + 512 * q;
            int i = p >> 5, jp = p & 31;
            const float* br = BTb + (size_t)i * KTOT + k0;
            float x = 0.f, y = 0.f;
            if (jp * 2 < kw)     x = br[jp * 2];
            if (jp * 2 + 1 < kw) y = br[jp * 2 + 1];
            uint32_t hp = cvt2(x, y);
            float h0 = __uint_as_float(hp << 16);
            float h1 = __uint_as_float(hp & 0xFFFF0000u);
            uint32_t lp = cvt2(x - h0, y - h1);
            *(uint32_t*)(smraw + OFF2_BH + (uint32_t)i * TSTR + jp * 4) = hp;
            *(uint32_t*)(smraw + OFF2_BL + (uint32_t)i * TSTR + jp * 4) = lp;
        }
        __syncthreads();

#pragma unroll
        for (int ks = 0; ks < 4; ks++) {
            uint32_t ah0[4], ah1[4], al0[4], al1[4];
            ldsm4(ah0, AbH + ks * 32u);
            ldsm4(ah1, AbH + 2304u + ks * 32u);      // +16 rows
            ldsm4(al0, AbL + ks * 32u);
            ldsm4(al1, AbL + 2304u + ks * 32u);
            uint32_t bh[2][4], bl[2][4];
#pragma unroll
            for (int np = 0; np < 2; np++) {
                ldsm4(bh[np], BbH + (uint32_t)np * 2304u + ks * 32u);
                ldsm4(bl[np], BbL + (uint32_t)np * 2304u + ks * 32u);
            }
#pragma unroll
            for (int nt = 0; nt < 4; nt++) {
                uint32_t b0h = bh[nt >> 1][(nt & 1) * 2];
                uint32_t b1h = bh[nt >> 1][(nt & 1) * 2 + 1];
                uint32_t b0l = bl[nt >> 1][(nt & 1) * 2];
                uint32_t b1l = bl[nt >> 1][(nt & 1) * 2 + 1];
                mma_bf16(acc[0][nt], ah0, b0h, b1h);   // AH*BH
                mma_bf16(acc[1][nt], ah1, b0h, b1h);
                mma_bf16(acc[0][nt], ah0, b0l, b1l);   // AH*BL
                mma_bf16(acc[1][nt], ah1, b0l, b1l);
                mma_bf16(acc[0][nt], al0, b0h, b1h);   // AL*BH
                mma_bf16(acc[1][nt], al1, b0h, b1h);
            }
        }
    }

    // ---- epilogue: partial write [z][b][r][i] ----
#pragma unroll
    for (int ms = 0; ms < 2; ms++) {
        int rA = r0 + warpM + ms * 16 + (lane >> 2);
        int rB = rA + 8;
#pragma unroll
        for (int nt = 0; nt < 4; nt++) {
            int col = warpN + nt * 8 + (lane & 3) * 2;
            if (rA < ROWS)
                *(float2*)&out[((size_t)z * BDIM * ROWS + (size_t)b * ROWS + rA)
                               * HDIM + col] =
                    make_float2(acc[ms][nt][0], acc[ms][nt][1]);
            if (rB < ROWS)
                *(float2*)&out[((size_t)z * BDIM * ROWS + (size_t)b * ROWS + rB)
                               * HDIM + col] =
                    make_float2(acc[ms][nt][2], acc[ms][nt][3]);
        }
    }
}

// ---------------------------------------------------------------------------
// Prep: split EN into bf16 hi/lo planes, plain [h][i][j]
// ---------------------------------------------------------------------------
__global__ void __launch_bounds__(256) k_prep(const float* __restrict__ EN) {
    int h = blockIdx.x;
    int t = threadIdx.x;
    const float* src = EN + (size_t)h * 16384;
    unsigned short* dh = g_ENhi + (size_t)h * 16384;
    unsigned short* dl = g_ENlo + (size_t)h * 16384;
    for (int idx = t; idx < 16384; idx += 256) {
        float v = src[idx];
        __nv_bfloat16 hb = __float2bfloat16(v);
        float hf = __bfloat162float(hb);
        __nv_bfloat16 lb = __float2bfloat16(v - hf);
        dh[idx] = *(unsigned short*)&hb;
        dl[idx] = *(unsigned short*)&lb;
    }
}

// ---------------------------------------------------------------------------
// Tensor-core econv (r8-proven inner loop: per-h A ldsm from smem, no hoist).
// A-build sums the ZN2E split-K partials directly (k_red fused away).
// B (EN planes) double-buffered via cp.async. 512 threads, warp tile 32x32.
// ---------------------------------------------------------------------------
#define ASTRB 272u
#define PLANE 34816u
#define OFF_AH 0u
#define OFF_AL 34816u
#define OFF_B  69632u
#define OFF_EV 208896u
#define SM_ECONV 225280u

__global__ void __launch_bounds__(512) k_econv_tc(const float* __restrict__ ev,
                                                  const unsigned short* __restrict__ ENhi,
                                                  const unsigned short* __restrict__ ENlo,
                                                  float* __restrict__ newp) {
    extern __shared__ char smraw[];
    uint32_t base32 = smem_u32(smraw);
    float* evs = (float*)(smraw + OFF_EV);

    int t = threadIdx.x;
    int lane = t & 31, w = t >> 5;
    int r0 = blockIdx.x * 128;
    int hbase = blockIdx.y * NH_PER;

    // ---- issue stage-0 B copy immediately (overlaps A build) ----
    {
        const char* sH = (const char*)(ENhi + (size_t)hbase * 16384);
        const char* sL = (const char*)(ENlo + (size_t)hbase * 16384);
        uint32_t dst = base32 + OFF_B;
#pragma unroll
        for (int k = 0; k < 4; k++) {
            int f = t + 512 * k;
            uint32_t i = (uint32_t)(f >> 4), seg = (uint32_t)(f & 15);
            uint32_t o = i * ASTRB + seg * 16u;
            cp16(dst + o,          sH + (size_t)f * 16);
            cp16(dst + PLANE + o,  sL + (size_t)f * 16);
        }
        cp_commit();
    }

    // ---- build A planes: emb = sum_z embp[z], split hi/lo bf16 ----
#pragma unroll 4
    for (int k = 0; k < 16; k++) {
        int p = t + 512 * k;
        int m = p >> 6, jp = p & 63;
        int r = r0 + m;
        float ex = 0.f, ey = 0.f;
        if (r < RTOT) {
#pragma unroll
            for (int z = 0; z < ZN2E; z++) {
                float2 v = *(const float2*)&g_embp[((size_t)z * RTOT + r) * HDIM
                                                   + jp * 2];
                ex += v.x; ey += v.y;
            }
        }
        uint32_t hp = cvt2(ex, ey);
        float h0 = __uint_as_float(hp << 16);
        float h1 = __uint_as_float(hp & 0xFFFF0000u);
        uint32_t lp = cvt2(ex - h0, ey - h1);
        *(uint32_t*)(smraw + OFF_AH + (uint32_t)m * ASTRB + jp * 4) = hp;
        *(uint32_t*)(smraw + OFF_AL + (uint32_t)m * ASTRB + jp * 4) = lp;
    }
    // ---- stage ev slice ----
    for (int idx = t; idx < NH_PER * 128; idx += 512) {
        int hh = idx >> 7, m = idx & 127;
        int r = r0 + m;
        evs[hh * 128 + m] = (r < RTOT) ? ev[(size_t)r * HDIM + hbase + hh] : 0.f;
    }

    float acc[2][4][4];
#pragma unroll
    for (int ms = 0; ms < 2; ms++)
#pragma unroll
        for (int nt = 0; nt < 4; nt++)
#pragma unroll
            for (int q = 0; q < 4; q++) acc[ms][nt][q] = 0.f;

    int warpM = (w & 3) * 32;
    int warpN = (w >> 2) * 32;
    uint32_t aoff = (uint32_t)(warpM + (lane & 15)) * ASTRB + (uint32_t)(lane >> 4) * 16u;
    uint32_t boff = (uint32_t)(warpN + ((lane >> 4) & 1) * 8 + (lane & 7)) * ASTRB
                  + (uint32_t)((lane >> 3) & 1) * 16u;
    uint32_t AbH = base32 + OFF_AH + aoff;
    uint32_t AbL = base32 + OFF_AL + aoff;

    int rl0 = warpM + (lane >> 2);

    for (int hh = 0; hh < NH_PER; hh++) {
        int s = hh & 1;
        cp_wait0();
        __syncthreads();                 // stage-s B visible; readers of 1-s done
                                         // (also covers A-plane/evs visibility at hh=0)
        if (hh + 1 < NH_PER) {
            const char* sH = (const char*)(ENhi + (size_t)(hbase + hh + 1) * 16384);
            const char* sL = (const char*)(ENlo + (size_t)(hbase + hh + 1) * 16384);
            uint32_t dst = base32 + OFF_B + (uint32_t)(1 - s) * 69632u;
#pragma unroll
            for (int k = 0; k < 4; k++) {
                int f = t + 512 * k;
                uint32_t i = (uint32_t)(f >> 4), seg = (uint32_t)(f & 15);
                uint32_t o = i * ASTRB + seg * 16u;
                cp16(dst + o,         sH + (size_t)f * 16);
                cp16(dst + PLANE + o, sL + (size_t)f * 16);
            }
            cp_commit();
        }

        uint32_t BbH = base32 + OFF_B + (uint32_t)s * 69632u + boff;
        uint32_t BbL = BbH + PLANE;

        float tt[2][4][4];
#pragma unroll
        for (int ms = 0; ms < 2; ms++)
#pragma unroll
            for (int nt = 0; nt < 4; nt++)
#pragma unroll
                for (int q = 0; q < 4; q++) tt[ms][nt][q] = 0.f;

#pragma unroll
        for (int ks = 0; ks < 8; ks++) {
            uint32_t ah0[4], ah1[4], al0[4], al1[4];
            ldsm4(ah0, AbH + ks * 32u);
            ldsm4(ah1, AbH + 4352u + ks * 32u);
            ldsm4(al0, AbL + ks * 32u);
            ldsm4(al1, AbL + 4352u + ks * 32u);
            uint32_t bh[2][4], bl[2][4];
#pragma unroll
            for (int np = 0; np < 2; np++) {
                ldsm4(bh[np], BbH + (uint32_t)np * 4352u + ks * 32u);
                ldsm4(bl[np], BbL + (uint32_t)np * 4352u + ks * 32u);
            }
#pragma unroll
            for (int nt = 0; nt < 4; nt++) {
                uint32_t b0h = bh[nt >> 1][(nt & 1) * 2];
                uint32_t b1h = bh[nt >> 1][(nt & 1) * 2 + 1];
                uint32_t b0l = bl[nt >> 1][(nt & 1) * 2];
                uint32_t b1l = bl[nt >> 1][(nt & 1) * 2 + 1];
                mma_bf16(tt[0][nt], ah0, b0h, b1h);
                mma_bf16(tt[1][nt], ah1, b0h, b1h);
                mma_bf16(tt[0][nt], ah0, b0l, b1l);
                mma_bf16(tt[1][nt], ah1, b0l, b1l);
                mma_bf16(tt[0][nt], al0, b0h, b1h);
                mma_bf16(tt[1][nt], al1, b0h, b1h);
            }
        }

        const float* evh = evs + hh * 128;
        float ev0A = evh[rl0];
        float ev0B = evh[rl0 + 8];
        float ev1A = evh[rl0 + 16];
        float ev1B = evh[rl0 + 24];
#pragma unroll
        for (int nt = 0; nt < 4; nt++) {
            acc[0][nt][0] += ev0A * tt[0][nt][0];
            acc[0][nt][1] += ev0A * tt[0][nt][1];
            acc[0][nt][2] += ev0B * tt[0][nt][2];
            acc[0][nt][3] += ev0B * tt[0][nt][3];
            acc[1][nt][0] += ev1A * tt[1][nt][0];
            acc[1][nt][1] += ev1A * tt[1][nt][1];
            acc[1][nt][2] += ev1B * tt[1][nt][2];
            acc[1][nt][3] += ev1B * tt[1][nt][3];
        }
    }

    size_t obase = (size_t)blockIdx.y * RTOT * HDIM;
#pragma unroll
    for (int ms = 0; ms < 2; ms++) {
        int rA = r0 + warpM + ms * 16 + (lane >> 2);
        int rB = rA + 8;
#pragma unroll
        for (int nt = 0; nt < 4; nt++) {
            int col = warpN + nt * 8 + (lane & 3) * 2;
            if (rA < RTOT)
                *(float2*)&newp[obase + (size_t)rA * HDIM + col] =
                    make_float2(acc[ms][nt][0], acc[ms][nt][1]);
            if (rB < RTOT)
                *(float2*)&newp[obase + (size_t)rB * HDIM + col] =
                    make_float2(acc[ms][nt][2], acc[ms][nt][3]);
        }
    }
}

// ---------------------------------------------------------------------------
// Fused HSPLIT-reduce + transpose: g_newT[b][i][e] = sum_hs newp[hs][b*E+e][i]
// Tiled 32x32, coalesced read and write. grid (63, 4, BDIM), 256 thr.
// ---------------------------------------------------------------------------
__global__ void __launch_bounds__(256) k_nredT(const float* __restrict__ newp) {
    __shared__ float tile[32][33];
    int b  = blockIdx.z;
    int e0 = blockIdx.x * 32, i0 = blockIdx.y * 32;
    int tx = threadIdx.x & 31, ty = threadIdx.x >> 5;

    for (int rr = ty; rr < 32; rr += 8) {
        int e = e0 + rr;
        float s = 0.f;
        if (e < EDIM) {
            size_t base = ((size_t)b * EDIM + e) * HDIM + i0 + tx;
#pragma unroll
            for (int z = 0; z < HSPLIT; z++)
                s += newp[(size_t)z * RTOT * HDIM + base];
        }
        tile[rr][tx] = s;
    }
    __syncthreads();
    for (int cc = ty; cc < 32; cc += 8) {
        int i = i0 + cc;
        int e = e0 + tx;
        if (e < EDIM)
            g_newT[((size_t)b * HDIM + i) * EDIM + e] = tile[tx][cc];
    }
}

__global__ void __launch_bounds__(256) k_norm(const float* __restrict__ e2n) {
    __shared__ float red[256];
    int row = blockIdx.x;
    const float* p = e2n + (size_t)row * EDIM;
    float s = 0.f;
    for (int e = threadIdx.x; e < EDIM; e += 256) s += p[e];
    red[threadIdx.x] = s;
    __syncthreads();
    for (int o = 128; o > 0; o >>= 1) {
        if (threadIdx.x < o) red[threadIdx.x] += red[threadIdx.x + o];
        __syncthreads();
    }
    if (threadIdx.x == 0) g_inv[row] = 1.f / (1.f + red[0]);
}

// out = (sum_z g_aggp[z] + node_state) * g_inv    (grid 250 exact)
__global__ void __launch_bounds__(256) k_fin(const float* __restrict__ ns,
                                             float* __restrict__ out) {
    const size_t STR = (size_t)BDIM * NDIM * HDIM / 4;
    size_t f = (size_t)blockIdx.x * 256 + threadIdx.x;
    const float4* p = (const float4*)g_aggp;
    float4 s = p[f];
#pragma unroll
    for (int z = 1; z < ZAGG; z++) {
        float4 v = p[z * STR + f];
        s.x += v.x; s.y += v.y; s.z += v.z; s.w += v.w;
    }
    float4 n4 = ((const float4*)ns)[f];
    float inv = g_inv[(f * 4) >> 7];
    float4 o;
    o.x = (s.x + n4.x) * inv;
    o.y = (s.y + n4.y) * inv;
    o.z = (s.z + n4.z) * inv;
    o.w = (s.w + n4.w) * inv;
    ((float4*)out)[f] = o;
}

// ---------------------------------------------------------------------------
extern "C" void kernel_launch(void* const* d_in, const int* in_sizes, int n_in,
                              void* d_out, int out_size) {
    const float* node_state   = (const float*)d_in[0];
    const float* edge_vec     = (const float*)d_in[1];
    const float* node2edge    = (const float*)d_in[2];
    const float* edge2node    = (const float*)d_in[3];
    const float* edge_network = (const float*)d_in[4];
    float* out = (float*)d_out;

    void* p_embp; cudaGetSymbolAddress(&p_embp, g_embp);
    void* p_newp; cudaGetSymbolAddress(&p_newp, g_newp);
    void* p_newT; cudaGetSymbolAddress(&p_newT, g_newT);
    void* p_aggp; cudaGetSymbolAddress(&p_aggp, g_aggp);
    void* p_nsT;  cudaGetSymbolAddress(&p_nsT,  g_nsT);
    void* p_enh;  cudaGetSymbolAddress(&p_enh,  g_ENhi);
    void* p_enl;  cudaGetSymbolAddress(&p_enl,  g_ENlo);

    cudaFuncSetAttribute(k_econv_tc, cudaFuncAttributeMaxDynamicSharedMemorySize,
                         SM_ECONV);
    cudaFuncSetAttribute(k_gemm_tc, cudaFuncAttributeMaxDynamicSharedMemorySize,
                         SM_GEMM2);

    // node_state^T: [b][1000][128] -> [b][128][1000]
    k_tr<<<dim3(32, 4, BDIM), dim3(32, 8)>>>(node_state, (float*)p_nsT,
                                             NDIM, HDIM);
    k_prep<<<HDIM, 256>>>(edge_network);
    // n2e: A=node2edge [b][E][N], BT=nsT -> partials (16,2,4)=128 blocks
    k_gemm_tc<<<dim3(16, BDIM, ZN2E), 512, SM_GEMM2>>>(node2edge,
                                                       (const float*)p_nsT,
                                                       (float*)p_embp,
                                                       EDIM, NDIM);
    // econv (A-build fuses the split-K reduce of g_embp)
    k_econv_tc<<<dim3(32, HSPLIT), 512, SM_ECONV>>>(edge_vec,
                                                    (const unsigned short*)p_enh,
                                                    (const unsigned short*)p_enl,
                                                    (float*)p_newp);
    // HSPLIT-reduce + transpose -> g_newT
    k_nredT<<<dim3(63, 4, BDIM), 256>>>((const float*)p_newp);
    // agg: A=edge2node [b][N][E], BT=g_newT -> partials (8,2,8)=128 blocks
    k_gemm_tc<<<dim3(8, BDIM, ZAGG), 512, SM_GEMM2>>>(edge2node,
                                                      (const float*)p_newT,
                                                      (float*)p_aggp,
                                                      NDIM, EDIM);
    k_norm<<<BDIM * NDIM, 256>>>(edge2node);
    k_fin<<<250, 256>>>(node_state, out);
}

// round 11
// speedup vs baseline: 1.3678x; 1.0478x over previous
#include <cuda_runtime.h>
#include <cuda_bf16.h>
#include <cstdint>

#define BDIM 2
#define NDIM 1000
#define EDIM 2000
#define HDIM 128
#define RTOT (BDIM * EDIM)          // 4000 flat rows

#define HSPLIT 4                    // h-splits for econv tensor kernel
#define NH_PER (HDIM / HSPLIT)      // 32 h per block

#define ZN2E 4                      // split-K for n2e tc-gemm (KP=1024 -> 256)
#define ZAGG 8                      // split-K for agg tc-gemm (KP=2048 -> 256)
#define KP1  1024                   // node2edge K=1000 padded
#define KP2  2048                   // edge2node K=2000 padded

// ---------------- scratch (device globals) ---------------------------------
__device__ float g_embp[(size_t)ZN2E * RTOT * HDIM];          // n2e partials
__device__ float g_newp[(size_t)HSPLIT * RTOT * HDIM];        // econv partials
__device__ float g_aggp[(size_t)ZAGG * BDIM * NDIM * HDIM];   // agg partials
__device__ float g_inv [(size_t)BDIM * NDIM];
// bf16 hi/lo operand planes (pre-split, K-padded)
__device__ unsigned short g_n2eH[(size_t)RTOT * KP1];
__device__ unsigned short g_n2eL[(size_t)RTOT * KP1];
__device__ unsigned short g_e2nH[(size_t)BDIM * NDIM * KP2];
__device__ unsigned short g_e2nL[(size_t)BDIM * NDIM * KP2];
__device__ unsigned short g_nsTH[(size_t)BDIM * HDIM * KP1];
__device__ unsigned short g_nsTL[(size_t)BDIM * HDIM * KP1];
__device__ unsigned short g_nwTH[(size_t)BDIM * HDIM * KP2];
__device__ unsigned short g_nwTL[(size_t)BDIM * HDIM * KP2];
// pre-split EN (bf16 hi/lo planes), plain [h][i][j] layout
__device__ unsigned short g_ENhi[(size_t)HDIM * 16384];
__device__ unsigned short g_ENlo[(size_t)HDIM * 16384];

// ---------------- helpers ---------------------------------------------------
__device__ __forceinline__ uint32_t smem_u32(const void* p) {
    uint32_t a;
    asm("{ .reg .u64 t; cvta.to.shared.u64 t, %1; cvt.u32.u64 %0, t; }"
        : "=r"(a) : "l"(p));
    return a;
}
__device__ __forceinline__ void ldsm4(uint32_t* r, uint32_t addr) {
    asm volatile("ldmatrix.sync.aligned.m8n8.x4.shared.b16 {%0,%1,%2,%3}, [%4];"
                 : "=r"(r[0]), "=r"(r[1]), "=r"(r[2]), "=r"(r[3]) : "r"(addr));
}
__device__ __forceinline__ void mma_bf16(float* d, const uint32_t* a,
                                         uint32_t b0, uint32_t b1) {
    asm volatile("mma.sync.aligned.m16n8k16.row.col.f32.bf16.bf16.f32 "
                 "{%0,%1,%2,%3}, {%4,%5,%6,%7}, {%8,%9}, {%0,%1,%2,%3};"
                 : "+f"(d[0]), "+f"(d[1]), "+f"(d[2]), "+f"(d[3])
                 : "r"(a[0]), "r"(a[1]), "r"(a[2]), "r"(a[3]), "r"(b0), "r"(b1));
}
__device__ __forceinline__ uint32_t cvt2(float lo, float hi) {
    uint32_t r;
    asm("cvt.rn.satfinite.bf16x2.f32 %0, %1, %2;" : "=r"(r) : "f"(hi), "f"(lo));
    return r;
}
__device__ __forceinline__ void cp16(uint32_t dst, const void* src) {
    asm volatile("cp.async.cg.shared.global [%0], [%1], 16;"
                 :: "r"(dst), "l"(src) : "memory");
}
__device__ __forceinline__ void cp_commit() {
    asm volatile("cp.async.commit_group;" ::: "memory");
}
__device__ __forceinline__ void cp_wait0() {
    asm volatile("cp.async.wait_group 0;" ::: "memory");
}
__device__ __forceinline__ void bf16_split(float v, unsigned short& h,
                                           unsigned short& l) {
    __nv_bfloat16 hb = __float2bfloat16(v);
    float hf = __bfloat162float(hb);
    __nv_bfloat16 lb = __float2bfloat16(v - hf);
    h = *(unsigned short*)&hb;
    l = *(unsigned short*)&lb;
}

// ---------------------------------------------------------------------------
// Row-wise split: in fp32 [rows][K] -> bf16 hi/lo [rows][KP] (zero-padded).
// do_norm: also g_inv[row] = 1/(1+rowsum).  One block per row.
// ---------------------------------------------------------------------------
__global__ void __launch_bounds__(256) k_splitrow(const float* __restrict__ in,
                                                  unsigned short* __restrict__ oh,
                                                  unsigned short* __restrict__ ol,
                                                  int K, int KPAD, int do_norm) {
    __shared__ float red[256];
    int row = blockIdx.x;
    const float* src = in + (size_t)row * K;
    unsigned short* dh = oh + (size_t)row * KPAD;
    unsigned short* dl = ol + (size_t)row * KPAD;
    float sum = 0.f;
    for (int idx = threadIdx.x; idx < KPAD; idx += 256) {
        float v = (idx < K) ? src[idx] : 0.f;
        sum += v;
        unsigned short h, l;
        bf16_split(v, h, l);
        dh[idx] = h; dl[idx] = l;
    }
    if (do_norm) {
        red[threadIdx.x] = sum;
        __syncthreads();
        for (int o = 128; o > 0; o >>= 1) {
            if (threadIdx.x < o) red[threadIdx.x] += red[threadIdx.x + o];
            __syncthreads();
        }
        if (threadIdx.x == 0) g_inv[row] = 1.f / (1.f + red[0]);
    }
}

// ---------------------------------------------------------------------------
// node_state [b][N][H] -> transposed bf16 hi/lo planes [b][H][KP1]
// ---------------------------------------------------------------------------
__global__ void __launch_bounds__(256) k_trs(const float* __restrict__ ns) {
    __shared__ float tile[32][33];
    int b  = blockIdx.z;
    int n0 = blockIdx.x * 32, h0 = blockIdx.y * 32;
    int tx = threadIdx.x & 31, ty = threadIdx.x >> 5;
    for (int rr = ty; rr < 32; rr += 8) {
        int n = n0 + rr;
        tile[rr][tx] = (n < NDIM) ? ns[((size_t)b * NDIM + n) * HDIM + h0 + tx]
                                  : 0.f;
    }
    __syncthreads();
    for (int cc = ty; cc < 32; cc += 8) {
        int h = h0 + cc, n = n0 + tx;           // n < 1024 = KP1 always
        unsigned short hh, ll;
        bf16_split(tile[tx][cc], hh, ll);
        size_t o = ((size_t)b * HDIM + h) * KP1 + n;
        g_nsTH[o] = hh; g_nsTL[o] = ll;
    }
}

// ---------------------------------------------------------------------------
// HSPLIT-reduce + transpose + split: g_nwT*[b][i][KP2] from newp partials
// grid (64, 4, BDIM) -> e tiles cover 2048 = KP2 (zero-padded past EDIM)
// ---------------------------------------------------------------------------
__global__ void __launch_bounds__(256) k_nredT(const float* __restrict__ newp) {
    __shared__ float tile[32][33];
    int b  = blockIdx.z;
    int e0 = blockIdx.x * 32, i0 = blockIdx.y * 32;
    int tx = threadIdx.x & 31, ty = threadIdx.x >> 5;
    for (int rr = ty; rr < 32; rr += 8) {
        int e = e0 + rr;
        float s = 0.f;
        if (e < EDIM) {
            size_t base = ((size_t)b * EDIM + e) * HDIM + i0 + tx;
#pragma unroll
            for (int z = 0; z < HSPLIT; z++)
                s += newp[(size_t)z * RTOT * HDIM + base];
        }
        tile[rr][tx] = s;
    }
    __syncthreads();
    for (int cc = ty; cc < 32; cc += 8) {
        int i = i0 + cc, e = e0 + tx;           // e < 2048 = KP2 always
        unsigned short hh, ll;
        bf16_split(tile[tx][cc], hh, ll);
        size_t o = ((size_t)b * HDIM + i) * KP2 + e;
        g_nwTH[o] = hh; g_nwTL[o] = ll;
    }
}

// ---------------------------------------------------------------------------
// Tensor-core split-K GEMM on PRE-SPLIT bf16 planes (no in-kernel cvt):
//   out[z][b][r][i] = sum_{k in z-chunk of 256} A[b][r][k] * BT[b][i][k]
// 512 threads, 16 warps, warp tile 32x32; cp.async double-buffered over kc.
// ---------------------------------------------------------------------------
#define TSTR 144u                   // (64 bf16 = 128B) + 16B pad
#define PL2  18432u                 // plane: 128*144
#define STG2 73728u                 // stage: 4 planes (AH, AL, BH, BL)
#define SM_GEMM2 147456u            // 2 stages

__global__ void __launch_bounds__(512) k_gemm_tc2(const unsigned short* __restrict__ Ah,
                                                  const unsigned short* __restrict__ Al,
                                                  const unsigned short* __restrict__ Bh,
                                                  const unsigned short* __restrict__ Bl,
                                                  float* __restrict__ out,
                                                  int ROWS, int KPAD) {
    extern __shared__ char smraw[];
    uint32_t base32 = smem_u32(smraw);

    int t = threadIdx.x;
    int lane = t & 31, w = t >> 5;
    int b  = blockIdx.y;
    int z  = blockIdx.z;
    int r0 = blockIdx.x * 128;

    const unsigned short* planes[4] = { Ah, Al, Bh, Bl };

    // tile copy for one kc into stage s
    auto copy_kc = [&](int kc, int s) {
        int k0 = z * 256 + kc * 64;
#pragma unroll
        for (int q = 0; q < 8; q++) {
            int f = t + 512 * q;            // 0..4095
            int pl = f >> 10;
            int idx = f & 1023;
            int row = idx >> 3, seg = idx & 7;
            uint32_t dst = base32 + (uint32_t)s * STG2 + (uint32_t)pl * PL2
                         + (uint32_t)row * TSTR + (uint32_t)seg * 16u;
            if (pl < 2) {                   // A planes: guard ragged M
                int rg = r0 + row;
                if (rg < ROWS) {
                    cp16(dst, planes[pl] + ((size_t)b * ROWS + rg) * KPAD
                              + k0 + seg * 8);
                } else {
                    *(uint4*)(smraw + (uint32_t)s * STG2 + (uint32_t)pl * PL2
                              + (uint32_t)row * TSTR + (uint32_t)seg * 16u)
                        = make_uint4(0, 0, 0, 0);
                }
            } else {                        // B planes: 128 rows exact
                cp16(dst, planes[pl] + ((size_t)b * HDIM + row) * KPAD
                          + k0 + seg * 8);
            }
        }
        cp_commit();
    };

    float acc[2][4][4];
#pragma unroll
    for (int ms = 0; ms < 2; ms++)
#pragma unroll
        for (int nt = 0; nt < 4; nt++)
#pragma unroll
            for (int q = 0; q < 4; q++) acc[ms][nt][q] = 0.f;

    int warpM = (w & 3) * 32;
    int warpN = (w >> 2) * 32;
    uint32_t aoff = (uint32_t)(warpM + (lane & 15)) * TSTR + (uint32_t)(lane >> 4) * 16u;
    uint32_t boff = (uint32_t)(warpN + ((lane >> 4) & 1) * 8 + (lane & 7)) * TSTR
                  + (uint32_t)((lane >> 3) & 1) * 16u;

    copy_kc(0, 0);                          // prologue

    for (int kc = 0; kc < 4; kc++) {
        int s = kc & 1;
        cp_wait0();
        __syncthreads();                    // stage s ready; stage 1-s free
        if (kc + 1 < 4) copy_kc(kc + 1, 1 - s);

        uint32_t AbH = base32 + (uint32_t)s * STG2 + aoff;
        uint32_t AbL = AbH + PL2;
        uint32_t BbH = base32 + (uint32_t)s * STG2 + 2u * PL2 + boff;
        uint32_t BbL = BbH + PL2;

#pragma unroll
        for (int ks = 0; ks < 4; ks++) {
            uint32_t ah0[4], ah1[4], al0[4], al1[4];
            ldsm4(ah0, AbH + ks * 32u);
            ldsm4(ah1, AbH + 2304u + ks * 32u);      // +16 rows
            ldsm4(al0, AbL + ks * 32u);
            ldsm4(al1, AbL + 2304u + ks * 32u);
            uint32_t bh[2][4], bl[2][4];
#pragma unroll
            for (int np = 0; np < 2; np++) {
                ldsm4(bh[np], BbH + (uint32_t)np * 2304u + ks * 32u);
                ldsm4(bl[np], BbL + (uint32_t)np * 2304u + ks * 32u);
            }
#pragma unroll
            for (int nt = 0; nt < 4; nt++) {
                uint32_t b0h = bh[nt >> 1][(nt & 1) * 2];
                uint32_t b1h = bh[nt >> 1][(nt & 1) * 2 + 1];
                uint32_t b0l = bl[nt >> 1][(nt & 1) * 2];
                uint32_t b1l = bl[nt >> 1][(nt & 1) * 2 + 1];
                mma_bf16(acc[0][nt], ah0, b0h, b1h);   // AH*BH
                mma_bf16(acc[1][nt], ah1, b0h, b1h);
                mma_bf16(acc[0][nt], ah0, b0l, b1l);   // AH*BL
                mma_bf16(acc[1][nt], ah1, b0l, b1l);
                mma_bf16(acc[0][nt], al0, b0h, b1h);   // AL*BH
                mma_bf16(acc[1][nt], al1, b0h, b1h);
            }
        }
        __syncthreads();                    // readers done before next overwrite
    }

    // ---- epilogue: partial write [z][b][r][i] ----
#pragma unroll
    for (int ms = 0; ms < 2; ms++) {
        int rA = r0 + warpM + ms * 16 + (lane >> 2);
        int rB = rA + 8;
#pragma unroll
        for (int nt = 0; nt < 4; nt++) {
            int col = warpN + nt * 8 + (lane & 3) * 2;
            if (rA < ROWS)
                *(float2*)&out[((size_t)z * BDIM * ROWS + (size_t)b * ROWS + rA)
                               * HDIM + col] =
                    make_float2(acc[ms][nt][0], acc[ms][nt][1]);
            if (rB < ROWS)
                *(float2*)&out[((size_t)z * BDIM * ROWS + (size_t)b * ROWS + rB)
                               * HDIM + col] =
                    make_float2(acc[ms][nt][2], acc[ms][nt][3]);
        }
    }
}

// ---------------------------------------------------------------------------
// Prep: split EN into bf16 hi/lo planes, plain [h][i][j]
// ---------------------------------------------------------------------------
__global__ void __launch_bounds__(256) k_prep(const float* __restrict__ EN) {
    int h = blockIdx.x;
    int t = threadIdx.x;
    const float* src = EN + (size_t)h * 16384;
    unsigned short* dh = g_ENhi + (size_t)h * 16384;
    unsigned short* dl = g_ENlo + (size_t)h * 16384;
    for (int idx = t; idx < 16384; idx += 256) {
        unsigned short hh, ll;
        bf16_split(src[idx], hh, ll);
        dh[idx] = hh; dl[idx] = ll;
    }
}

// ---------------------------------------------------------------------------
// Tensor-core econv (r10-proven, unchanged): per-h A ldsm from smem,
// B double-buffered via cp.async; A-build fuses the split-K reduce of g_embp.
// ---------------------------------------------------------------------------
#define ASTRB 272u
#define PLANE 34816u
#define OFF_AH 0u
#define OFF_AL 34816u
#define OFF_B  69632u
#define OFF_EV 208896u
#define SM_ECONV 225280u

__global__ void __launch_bounds__(512) k_econv_tc(const float* __restrict__ ev,
                                                  const unsigned short* __restrict__ ENhi,
                                                  const unsigned short* __restrict__ ENlo,
                                                  float* __restrict__ newp) {
    extern __shared__ char smraw[];
    uint32_t base32 = smem_u32(smraw);
    float* evs = (float*)(smraw + OFF_EV);

    int t = threadIdx.x;
    int lane = t & 31, w = t >> 5;
    int r0 = blockIdx.x * 128;
    int hbase = blockIdx.y * NH_PER;

    {
        const char* sH = (const char*)(ENhi + (size_t)hbase * 16384);
        const char* sL = (const char*)(ENlo + (size_t)hbase * 16384);
        uint32_t dst = base32 + OFF_B;
#pragma unroll
        for (int k = 0; k < 4; k++) {
            int f = t + 512 * k;
            uint32_t i = (uint32_t)(f >> 4), seg = (uint32_t)(f & 15);
            uint32_t o = i * ASTRB + seg * 16u;
            cp16(dst + o,          sH + (size_t)f * 16);
            cp16(dst + PLANE + o,  sL + (size_t)f * 16);
        }
        cp_commit();
    }

#pragma unroll 4
    for (int k = 0; k < 16; k++) {
        int p = t + 512 * k;
        int m = p >> 6, jp = p & 63;
        int r = r0 + m;
        float ex = 0.f, ey = 0.f;
        if (r < RTOT) {
#pragma unroll
            for (int z = 0; z < ZN2E; z++) {
                float2 v = *(const float2*)&g_embp[((size_t)z * RTOT + r) * HDIM
                                                   + jp * 2];
                ex += v.x; ey += v.y;
            }
        }
        uint32_t hp = cvt2(ex, ey);
        float h0 = __uint_as_float(hp << 16);
        float h1 = __uint_as_float(hp & 0xFFFF0000u);
        uint32_t lp = cvt2(ex - h0, ey - h1);
        *(uint32_t*)(smraw + OFF_AH + (uint32_t)m * ASTRB + jp * 4) = hp;
        *(uint32_t*)(smraw + OFF_AL + (uint32_t)m * ASTRB + jp * 4) = lp;
    }
    for (int idx = t; idx < NH_PER * 128; idx += 512) {
        int hh = idx >> 7, m = idx & 127;
        int r = r0 + m;
        evs[hh * 128 + m] = (r < RTOT) ? ev[(size_t)r * HDIM + hbase + hh] : 0.f;
    }

    float acc[2][4][4];
#pragma unroll
    for (int ms = 0; ms < 2; ms++)
#pragma unroll
        for (int nt = 0; nt < 4; nt++)
#pragma unroll
            for (int q = 0; q < 4; q++) acc[ms][nt][q] = 0.f;

    int warpM = (w & 3) * 32;
    int warpN = (w >> 2) * 32;
    uint32_t aoff = (uint32_t)(warpM + (lane & 15)) * ASTRB + (uint32_t)(lane >> 4) * 16u;
    uint32_t boff = (uint32_t)(warpN + ((lane >> 4) & 1) * 8 + (lane & 7)) * ASTRB
                  + (uint32_t)((lane >> 3) & 1) * 16u;
    uint32_t AbH = base32 + OFF_AH + aoff;
    uint32_t AbL = base32 + OFF_AL + aoff;

    int rl0 = warpM + (lane >> 2);

    for (int hh = 0; hh < NH_PER; hh++) {
        int s = hh & 1;
        cp_wait0();
        __syncthreads();

        if (hh + 1 < NH_PER) {
            const char* sH = (const char*)(ENhi + (size_t)(hbase + hh + 1) * 16384);
            const char* sL = (const char*)(ENlo + (size_t)(hbase + hh + 1) * 16384);
            uint32_t dst = base32 + OFF_B + (uint32_t)(1 - s) * 69632u;
#pragma unroll
            for (int k = 0; k < 4; k++) {
                int f = t + 512 * k;
                uint32_t i = (uint32_t)(f >> 4), seg = (uint32_t)(f & 15);
                uint32_t o = i * ASTRB + seg * 16u;
                cp16(dst + o,         sH + (size_t)f * 16);
                cp16(dst + PLANE + o, sL + (size_t)f * 16);
            }
            cp_commit();
        }

        uint32_t BbH = base32 + OFF_B + (uint32_t)s * 69632u + boff;
        uint32_t BbL = BbH + PLANE;

        float tt[2][4][4];
#pragma unroll
        for (int ms = 0; ms < 2; ms++)
#pragma unroll
            for (int nt = 0; nt < 4; nt++)
#pragma unroll
                for (int q = 0; q < 4; q++) tt[ms][nt][q] = 0.f;

#pragma unroll
        for (int ks = 0; ks < 8; ks++) {
            uint32_t ah0[4], ah1[4], al0[4], al1[4];
            ldsm4(ah0, AbH + ks * 32u);
            ldsm4(ah1, AbH + 4352u + ks * 32u);
            ldsm4(al0, AbL + ks * 32u);
            ldsm4(al1, AbL + 4352u + ks * 32u);
            uint32_t bh[2][4], bl[2][4];
#pragma unroll
            for (int np = 0; np < 2; np++) {
                ldsm4(bh[np], BbH + (uint32_t)np * 4352u + ks * 32u);
                ldsm4(bl[np], BbL + (uint32_t)np * 4352u + ks * 32u);
            }
#pragma unroll
            for (int nt = 0; nt < 4; nt++) {
                uint32_t b0h = bh[nt >> 1][(nt & 1) * 2];
                uint32_t b1h = bh[nt >> 1][(nt & 1) * 2 + 1];
                uint32_t b0l = bl[nt >> 1][(nt & 1) * 2];
                uint32_t b1l = bl[nt >> 1][(nt & 1) * 2 + 1];
                mma_bf16(tt[0][nt], ah0, b0h, b1h);
                mma_bf16(tt[1][nt], ah1, b0h, b1h);
                mma_bf16(tt[0][nt], ah0, b0l, b1l);
                mma_bf16(tt[1][nt], ah1, b0l, b1l);
                mma_bf16(tt[0][nt], al0, b0h, b1h);
                mma_bf16(tt[1][nt], al1, b0h, b1h);
            }
        }

        const float* evh = evs + hh * 128;
        float ev0A = evh[rl0];
        float ev0B = evh[rl0 + 8];
        float ev1A = evh[rl0 + 16];
        float ev1B = evh[rl0 + 24];
#pragma unroll
        for (int nt = 0; nt < 4; nt++) {
            acc[0][nt][0] += ev0A * tt[0][nt][0];
            acc[0][nt][1] += ev0A * tt[0][nt][1];
            acc[0][nt][2] += ev0B * tt[0][nt][2];
            acc[0][nt][3] += ev0B * tt[0][nt][3];
            acc[1][nt][0] += ev1A * tt[1][nt][0];
            acc[1][nt][1] += ev1A * tt[1][nt][1];
            acc[1][nt][2] += ev1B * tt[1][nt][2];
            acc[1][nt][3] += ev1B * tt[1][nt][3];
        }
    }

    size_t obase = (size_t)blockIdx.y * RTOT * HDIM;
#pragma unroll
    for (int ms = 0; ms < 2; ms++) {
        int rA = r0 + warpM + ms * 16 + (lane >> 2);
        int rB = rA + 8;
#pragma unroll
        for (int nt = 0; nt < 4; nt++) {
            int col = warpN + nt * 8 + (lane & 3) * 2;
            if (rA < RTOT)
                *(float2*)&newp[obase + (size_t)rA * HDIM + col] =
                    make_float2(acc[ms][nt][0], acc[ms][nt][1]);
            if (rB < RTOT)
                *(float2*)&newp[obase + (size_t)rB * HDIM + col] =
                    make_float2(acc[ms][nt][2], acc[ms][nt][3]);
        }
    }
}

// out = (sum_z g_aggp[z] + node_state) * g_inv    (grid 250 exact)
__global__ void __launch_bounds__(256) k_fin(const float* __restrict__ ns,
                                             float* __restrict__ out) {
    const size_t STR = (size_t)BDIM * NDIM * HDIM / 4;
    size_t f = (size_t)blockIdx.x * 256 + threadIdx.x;
    const float4* p = (const float4*)g_aggp;
    float4 s = p[f];
#pragma unroll
    for (int z = 1; z < ZAGG; z++) {
        float4 v = p[z * STR + f];
        s.x += v.x; s.y += v.y; s.z += v.z; s.w += v.w;
    }
    float4 n4 = ((const float4*)ns)[f];
    float inv = g_inv[(f * 4) >> 7];
    float4 o;
    o.x = (s.x + n4.x) * inv;
    o.y = (s.y + n4.y) * inv;
    o.z = (s.z + n4.z) * inv;
    o.w = (s.w + n4.w) * inv;
    ((float4*)out)[f] = o;
}

// ---------------------------------------------------------------------------
extern "C" void kernel_launch(void* const* d_in, const int* in_sizes, int n_in,
                              void* d_out, int out_size) {
    const float* node_state   = (const float*)d_in[0];
    const float* edge_vec     = (const float*)d_in[1];
    const float* node2edge    = (const float*)d_in[2];
    const float* edge2node    = (const float*)d_in[3];
    const float* edge_network = (const float*)d_in[4];
    float* out = (float*)d_out;

    void* p_embp; cudaGetSymbolAddress(&p_embp, g_embp);
    void* p_newp; cudaGetSymbolAddress(&p_newp, g_newp);
    void* p_aggp; cudaGetSymbolAddress(&p_aggp, g_aggp);
    void* p_n2eH; cudaGetSymbolAddress(&p_n2eH, g_n2eH);
    void* p_n2eL; cudaGetSymbolAddress(&p_n2eL, g_n2eL);
    void* p_e2nH; cudaGetSymbolAddress(&p_e2nH, g_e2nH);
    void* p_e2nL; cudaGetSymbolAddress(&p_e2nL, g_e2nL);
    void* p_nsTH; cudaGetSymbolAddress(&p_nsTH, g_nsTH);
    void* p_nsTL; cudaGetSymbolAddress(&p_nsTL, g_nsTL);
    void* p_nwTH; cudaGetSymbolAddress(&p_nwTH, g_nwTH);
    void* p_nwTL; cudaGetSymbolAddress(&p_nwTL, g_nwTL);
    void* p_enh;  cudaGetSymbolAddress(&p_enh,  g_ENhi);
    void* p_enl;  cudaGetSymbolAddress(&p_enl,  g_ENlo);

    cudaFuncSetAttribute(k_econv_tc, cudaFuncAttributeMaxDynamicSharedMemorySize,
                         SM_ECONV);
    cudaFuncSetAttribute(k_gemm_tc2, cudaFuncAttributeMaxDynamicSharedMemorySize,
                         SM_GEMM2);

    k_prep<<<HDIM, 256>>>(edge_network);
    // operand pre-splits (bf16 hi/lo, K-padded)
    k_splitrow<<<RTOT, 256>>>(node2edge, (unsigned short*)p_n2eH,
                              (unsigned short*)p_n2eL, NDIM, KP1, 0);
    k_splitrow<<<BDIM * NDIM, 256>>>(edge2node, (unsigned short*)p_e2nH,
                                     (unsigned short*)p_e2nL, EDIM, KP2, 1);
    k_trs<<<dim3(32, 4, BDIM), 256>>>(node_state);
    // n2e: (16,2,4) = 128 blocks
    k_gemm_tc2<<<dim3(16, BDIM, ZN2E), 512, SM_GEMM2>>>(
        (const unsigned short*)p_n2eH, (const unsigned short*)p_n2eL,
        (const unsigned short*)p_nsTH, (const unsigned short*)p_nsTL,
        (float*)p_embp, EDIM, KP1);
    // econv (A-build fuses the split-K reduce of g_embp)
    k_econv_tc<<<dim3(32, HSPLIT), 512, SM_ECONV>>>(edge_vec,
                                                    (const unsigned short*)p_enh,
                                                    (const unsigned short*)p_enl,
                                                    (float*)p_newp);
    // HSPLIT-reduce + transpose + split -> g_nwT planes
    k_nredT<<<dim3(64, 4, BDIM), 256>>>((const float*)p_newp);
    // agg: (8,2,8) = 128 blocks
    k_gemm_tc2<<<dim3(8, BDIM, ZAGG), 512, SM_GEMM2>>>(
        (const unsigned short*)p_e2nH, (const unsigned short*)p_e2nL,
        (const unsigned short*)p_nwTH, (const unsigned short*)p_nwTL,
        (float*)p_aggp, NDIM, KP2);
    k_fin<<<250, 256>>>(node_state, out);
}

// round 13
// speedup vs baseline: 1.7903x; 1.3089x over previous
#include <cuda_runtime.h>
#include <cuda_bf16.h>
#include <cuda_fp16.h>
#include <cstdint>

#define BDIM 2
#define NDIM 1000
#define EDIM 2000
#define HDIM 128
#define RTOT (BDIM * EDIM)          // 4000 flat rows

#define HSPLIT 4                    // h-splits for econv tensor kernel
#define NH_PER (HDIM / HSPLIT)      // 32 h per block

#define ZN2E 4                      // split-K for n2e tc-gemm (KP=1024 -> 256)
#define ZAGG 8                      // split-K for agg tc-gemm (KP=2048 -> 256)
#define KP1  1024                   // node2edge K=1000 padded
#define KP2  2048                   // edge2node K=2000 padded

// ---------------- scratch (device globals) ---------------------------------
__device__ float g_embp[(size_t)ZN2E * RTOT * HDIM];          // n2e partials
__device__ float g_newp[(size_t)HSPLIT * RTOT * HDIM];        // econv partials
__device__ float g_aggp[(size_t)ZAGG * BDIM * NDIM * HDIM];   // agg partials
__device__ float g_inv [(size_t)BDIM * NDIM];
// bf16 hi/lo operand planes (pre-split, K-padded) for glue GEMMs
__device__ unsigned short g_n2eH[(size_t)RTOT * KP1];
__device__ unsigned short g_n2eL[(size_t)RTOT * KP1];
__device__ unsigned short g_e2nH[(size_t)BDIM * NDIM * KP2];
__device__ unsigned short g_e2nL[(size_t)BDIM * NDIM * KP2];
__device__ unsigned short g_nsTH[(size_t)BDIM * HDIM * KP1];
__device__ unsigned short g_nsTL[(size_t)BDIM * HDIM * KP1];
__device__ unsigned short g_nwTH[(size_t)BDIM * HDIM * KP2];
__device__ unsigned short g_nwTL[(size_t)BDIM * HDIM * KP2];
// EN as single fp16 plane, plain [h][i][j] layout (econv B operand)
__device__ unsigned short g_ENfp[(size_t)HDIM * 16384];

// ---------------- helpers ---------------------------------------------------
__device__ __forceinline__ uint32_t smem_u32(const void* p) {
    uint32_t a;
    asm("{ .reg .u64 t; cvta.to.shared.u64 t, %1; cvt.u32.u64 %0, t; }"
        : "=r"(a) : "l"(p));
    return a;
}
__device__ __forceinline__ void ldsm4(uint32_t* r, uint32_t addr) {
    asm volatile("ldmatrix.sync.aligned.m8n8.x4.shared.b16 {%0,%1,%2,%3}, [%4];"
                 : "=r"(r[0]), "=r"(r[1]), "=r"(r[2]), "=r"(r[3]) : "r"(addr));
}
__device__ __forceinline__ void mma_bf16(float* d, const uint32_t* a,
                                         uint32_t b0, uint32_t b1) {
    asm volatile("mma.sync.aligned.m16n8k16.row.col.f32.bf16.bf16.f32 "
                 "{%0,%1,%2,%3}, {%4,%5,%6,%7}, {%8,%9}, {%0,%1,%2,%3};"
                 : "+f"(d[0]), "+f"(d[1]), "+f"(d[2]), "+f"(d[3])
                 : "r"(a[0]), "r"(a[1]), "r"(a[2]), "r"(a[3]), "r"(b0), "r"(b1));
}
__device__ __forceinline__ void mma_f16(float* d, const uint32_t* a,
                                        uint32_t b0, uint32_t b1) {
    asm volatile("mma.sync.aligned.m16n8k16.row.col.f32.f16.f16.f32 "
                 "{%0,%1,%2,%3}, {%4,%5,%6,%7}, {%8,%9}, {%0,%1,%2,%3};"
                 : "+f"(d[0]), "+f"(d[1]), "+f"(d[2]), "+f"(d[3])
                 : "r"(a[0]), "r"(a[1]), "r"(a[2]), "r"(a[3]), "r"(b0), "r"(b1));
}
__device__ __forceinline__ void cp16(uint32_t dst, const void* src) {
    asm volatile("cp.async.cg.shared.global [%0], [%1], 16;"
                 :: "r"(dst), "l"(src) : "memory");
}
__device__ __forceinline__ void cp_commit() {
    asm volatile("cp.async.commit_group;" ::: "memory");
}
__device__ __forceinline__ void cp_wait0() {
    asm volatile("cp.async.wait_group 0;" ::: "memory");
}
__device__ __forceinline__ void bf16_split(float v, unsigned short& h,
                                           unsigned short& l) {
    __nv_bfloat16 hb = __float2bfloat16(v);
    float hf = __bfloat162float(hb);
    __nv_bfloat16 lb = __float2bfloat16(v - hf);
    h = *(unsigned short*)&hb;
    l = *(unsigned short*)&lb;
}

// ---------------------------------------------------------------------------
// Row-wise split: in fp32 [rows][K] -> bf16 hi/lo [rows][KP] (zero-padded).
// do_norm: also g_inv[row] = 1/(1+rowsum).  One block per row.
// ---------------------------------------------------------------------------
__global__ void __launch_bounds__(256) k_splitrow(const float* __restrict__ in,
                                                  unsigned short* __restrict__ oh,
                                                  unsigned short* __restrict__ ol,
                                                  int K, int KPAD, int do_norm) {
    __shared__ float red[256];
    int row = blockIdx.x;
    const float* src = in + (size_t)row * K;
    unsigned short* dh = oh + (size_t)row * KPAD;
    unsigned short* dl = ol + (size_t)row * KPAD;
    float sum = 0.f;
    for (int idx = threadIdx.x; idx < KPAD; idx += 256) {
        float v = (idx < K) ? src[idx] : 0.f;
        sum += v;
        unsigned short h, l;
        bf16_split(v, h, l);
        dh[idx] = h; dl[idx] = l;
    }
    if (do_norm) {
        red[threadIdx.x] = sum;
        __syncthreads();
        for (int o = 128; o > 0; o >>= 1) {
            if (threadIdx.x < o) red[threadIdx.x] += red[threadIdx.x + o];
            __syncthreads();
        }
        if (threadIdx.x == 0) g_inv[row] = 1.f / (1.f + red[0]);
    }
}

// ---------------------------------------------------------------------------
// node_state [b][N][H] -> transposed bf16 hi/lo planes [b][H][KP1]
// ---------------------------------------------------------------------------
__global__ void __launch_bounds__(256) k_trs(const float* __restrict__ ns) {
    __shared__ float tile[32][33];
    int b  = blockIdx.z;
    int n0 = blockIdx.x * 32, h0 = blockIdx.y * 32;
    int tx = threadIdx.x & 31, ty = threadIdx.x >> 5;
    for (int rr = ty; rr < 32; rr += 8) {
        int n = n0 + rr;
        tile[rr][tx] = (n < NDIM) ? ns[((size_t)b * NDIM + n) * HDIM + h0 + tx]
                                  : 0.f;
    }
    __syncthreads();
    for (int cc = ty; cc < 32; cc += 8) {
        int h = h0 + cc, n = n0 + tx;           // n < 1024 = KP1 always
        unsigned short hh, ll;
        bf16_split(tile[tx][cc], hh, ll);
        size_t o = ((size_t)b * HDIM + h) * KP1 + n;
        g_nsTH[o] = hh; g_nsTL[o] = ll;
    }
}

// ---------------------------------------------------------------------------
// HSPLIT-reduce + transpose + split: g_nwT*[b][i][KP2] from newp partials
// grid (64, 4, BDIM) -> e tiles cover 2048 = KP2 (zero-padded past EDIM)
// ---------------------------------------------------------------------------
__global__ void __launch_bounds__(256) k_nredT(const float* __restrict__ newp) {
    __shared__ float tile[32][33];
    int b  = blockIdx.z;
    int e0 = blockIdx.x * 32, i0 = blockIdx.y * 32;
    int tx = threadIdx.x & 31, ty = threadIdx.x >> 5;
    for (int rr = ty; rr < 32; rr += 8) {
        int e = e0 + rr;
        float s = 0.f;
        if (e < EDIM) {
            size_t base = ((size_t)b * EDIM + e) * HDIM + i0 + tx;
#pragma unroll
            for (int z = 0; z < HSPLIT; z++)
                s += newp[(size_t)z * RTOT * HDIM + base];
        }
        tile[rr][tx] = s;
    }
    __syncthreads();
    for (int cc = ty; cc < 32; cc += 8) {
        int i = i0 + cc, e = e0 + tx;           // e < 2048 = KP2 always
        unsigned short hh, ll;
        bf16_split(tile[tx][cc], hh, ll);
        size_t o = ((size_t)b * HDIM + i) * KP2 + e;
        g_nwTH[o] = hh; g_nwTL[o] = ll;
    }
}

// ---------------------------------------------------------------------------
// Tensor-core split-K GEMM on PRE-SPLIT bf16 planes (no in-kernel cvt):
//   out[z][b][r][i] = sum_{k in z-chunk of 256} A[b][r][k] * BT[b][i][k]
// 512 threads, 16 warps, warp tile 32x32; cp.async double-buffered over kc.
// ---------------------------------------------------------------------------
#define TSTR 144u                   // (64 bf16 = 128B) + 16B pad
#define PL2  18432u                 // plane: 128*144
#define STG2 73728u                 // stage: 4 planes (AH, AL, BH, BL)
#define SM_GEMM2 147456u            // 2 stages

__global__ void __launch_bounds__(512) k_gemm_tc2(const unsigned short* __restrict__ Ah,
                                                  const unsigned short* __restrict__ Al,
                                                  const unsigned short* __restrict__ Bh,
                                                  const unsigned short* __restrict__ Bl,
                                                  float* __restrict__ out,
                                                  int ROWS, int KPAD) {
    extern __shared__ char smraw[];
    uint32_t base32 = smem_u32(smraw);

    int t = threadIdx.x;
    int lane = t & 31, w = t >> 5;
    int b  = blockIdx.y;
    int z  = blockIdx.z;
    int r0 = blockIdx.x * 128;

    const unsigned short* planes[4] = { Ah, Al, Bh, Bl };

    auto copy_kc = [&](int kc, int s) {
        int k0 = z * 256 + kc * 64;
#pragma unroll
        for (int q = 0; q < 8; q++) {
            int f = t + 512 * q;            // 0..4095
            int pl = f >> 10;
            int idx = f & 1023;
            int row = idx >> 3, seg = idx & 7;
            uint32_t dst = base32 + (uint32_t)s * STG2 + (uint32_t)pl * PL2
                         + (uint32_t)row * TSTR + (uint32_t)seg * 16u;
            if (pl < 2) {                   // A planes: guard ragged M
                int rg = r0 + row;
                if (rg < ROWS) {
                    cp16(dst, planes[pl] + ((size_t)b * ROWS + rg) * KPAD
                              + k0 + seg * 8);
                } else {
                    *(uint4*)(smraw + (uint32_t)s * STG2 + (uint32_t)pl * PL2
                              + (uint32_t)row * TSTR + (uint32_t)seg * 16u)
                        = make_uint4(0, 0, 0, 0);
                }
            } else {                        // B planes: 128 rows exact
                cp16(dst, planes[pl] + ((size_t)b * HDIM + row) * KPAD
                          + k0 + seg * 8);
            }
        }
        cp_commit();
    };

    float acc[2][4][4];
#pragma unroll
    for (int ms = 0; ms < 2; ms++)
#pragma unroll
        for (int nt = 0; nt < 4; nt++)
#pragma unroll
            for (int q = 0; q < 4; q++) acc[ms][nt][q] = 0.f;

    int warpM = (w & 3) * 32;
    int warpN = (w >> 2) * 32;
    uint32_t aoff = (uint32_t)(warpM + (lane & 15)) * TSTR + (uint32_t)(lane >> 4) * 16u;
    uint32_t boff = (uint32_t)(warpN + ((lane >> 4) & 1) * 8 + (lane & 7)) * TSTR
                  + (uint32_t)((lane >> 3) & 1) * 16u;

    copy_kc(0, 0);                          // prologue

    for (int kc = 0; kc < 4; kc++) {
        int s = kc & 1;
        cp_wait0();
        __syncthreads();
        if (kc + 1 < 4) copy_kc(kc + 1, 1 - s);

        uint32_t AbH = base32 + (uint32_t)s * STG2 + aoff;
        uint32_t AbL = AbH + PL2;
        uint32_t BbH = base32 + (uint32_t)s * STG2 + 2u * PL2 + boff;
        uint32_t BbL = BbH + PL2;

#pragma unroll
        for (int ks = 0; ks < 4; ks++) {
            uint32_t ah0[4], ah1[4], al0[4], al1[4];
            ldsm4(ah0, AbH + ks * 32u);
            ldsm4(ah1, AbH + 2304u + ks * 32u);      // +16 rows
            ldsm4(al0, AbL + ks * 32u);
            ldsm4(al1, AbL + 2304u + ks * 32u);
            uint32_t bh[2][4], bl[2][4];
#pragma unroll
            for (int np = 0; np < 2; np++) {
                ldsm4(bh[np], BbH + (uint32_t)np * 2304u + ks * 32u);
                ldsm4(bl[np], BbL + (uint32_t)np * 2304u + ks * 32u);
            }
#pragma unroll
            for (int nt = 0; nt < 4; nt++) {
                uint32_t b0h = bh[nt >> 1][(nt & 1) * 2];
                uint32_t b1h = bh[nt >> 1][(nt & 1) * 2 + 1];
                uint32_t b0l = bl[nt >> 1][(nt & 1) * 2];
                uint32_t b1l = bl[nt >> 1][(nt & 1) * 2 + 1];
                mma_bf16(acc[0][nt], ah0, b0h, b1h);   // AH*BH
                mma_bf16(acc[1][nt], ah1, b0h, b1h);
                mma_bf16(acc[0][nt], ah0, b0l, b1l);   // AH*BL
                mma_bf16(acc[1][nt], ah1, b0l, b1l);
                mma_bf16(acc[0][nt], al0, b0h, b1h);   // AL*BH
                mma_bf16(acc[1][nt], al1, b0h, b1h);
            }
        }
        __syncthreads();
    }

#pragma unroll
    for (int ms = 0; ms < 2; ms++) {
        int rA = r0 + warpM + ms * 16 + (lane >> 2);
        int rB = rA + 8;
#pragma unroll
        for (int nt = 0; nt < 4; nt++) {
            int col = warpN + nt * 8 + (lane & 3) * 2;
            if (rA < ROWS)
                *(float2*)&out[((size_t)z * BDIM * ROWS + (size_t)b * ROWS + rA)
                               * HDIM + col] =
                    make_float2(acc[ms][nt][0], acc[ms][nt][1]);
            if (rB < ROWS)
                *(float2*)&out[((size_t)z * BDIM * ROWS + (size_t)b * ROWS + rB)
                               * HDIM + col] =
                    make_float2(acc[ms][nt][2], acc[ms][nt][3]);
        }
    }
}

// ---------------------------------------------------------------------------
// Prep: EN -> single fp16 plane, plain [h][i][j]
// ---------------------------------------------------------------------------
__global__ void __launch_bounds__(256) k_prep(const float* __restrict__ EN) {
    int h = blockIdx.x;
    int t = threadIdx.x;
    const float* src = EN + (size_t)h * 16384;
    unsigned short* dp = g_ENfp + (size_t)h * 16384;
    for (int idx = t; idx < 16384; idx += 256) {
        __half hv = __float2half_rn(src[idx]);
        dp[idx] = *(unsigned short*)&hv;
    }
}

// ---------------------------------------------------------------------------
// Tensor-core econv, fp16 2-term: A = emb split hi/lo fp16 (h-invariant, in
// smem), B = EN single fp16 plane (cp.async double-buffered).
//   tt = emb @ EN_h^T ; acc += ev[r,h] * tt
// A-build fuses the split-K reduce of g_embp. 512 threads, warp tile 32x32.
// ---------------------------------------------------------------------------
#define ASTRB 272u
#define PLANE 34816u
#define OFF_AH 0u
#define OFF_AL 34816u
#define OFF_B  69632u                // stage s at OFF_B + s*34816 (single plane)
#define OFF_EV 139264u               // float [NH_PER][128]
#define SM_ECONV 155648u

__global__ void __launch_bounds__(512) k_econv_tc(const float* __restrict__ ev,
                                                  const unsigned short* __restrict__ ENfp,
                                                  float* __restrict__ newp) {
    extern __shared__ char smraw[];
    uint32_t base32 = smem_u32(smraw);
    float* evs = (float*)(smraw + OFF_EV);

    int t = threadIdx.x;
    int lane = t & 31, w = t >> 5;
    int r0 = blockIdx.x * 128;
    int hbase = blockIdx.y * NH_PER;

    // ---- issue stage-0 B copy immediately (overlaps A build) ----
    {
        const char* sB = (const char*)(ENfp + (size_t)hbase * 16384);
        uint32_t dst = base32 + OFF_B;
#pragma unroll
        for (int k = 0; k < 4; k++) {
            int f = t + 512 * k;
            uint32_t i = (uint32_t)(f >> 4), seg = (uint32_t)(f & 15);
            cp16(dst + i * ASTRB + seg * 16u, sB + (size_t)f * 16);
        }
        cp_commit();
    }

    // ---- build A planes: emb = sum_z embp[z], split hi/lo fp16 ----
#pragma unroll 4
    for (int k = 0; k < 16; k++) {
        int p = t + 512 * k;
        int m = p >> 6, jp = p & 63;
        int r = r0 + m;
        float ex = 0.f, ey = 0.f;
        if (r < RTOT) {
#pragma unroll
            for (int z = 0; z < ZN2E; z++) {
                float2 v = *(const float2*)&g_embp[((size_t)z * RTOT + r) * HDIM
                                                   + jp * 2];
                ex += v.x; ey += v.y;
            }
        }
        __half hx = __float2half_rn(ex), hy = __float2half_rn(ey);
        __half lx = __float2half_rn(ex - __half2float(hx));
        __half ly = __float2half_rn(ey - __half2float(hy));
        __half2 hp = __halves2half2(hx, hy);   // low = ex, high = ey
        __half2 lp = __halves2half2(lx, ly);
        *(uint32_t*)(smraw + OFF_AH + (uint32_t)m * ASTRB + jp * 4)
            = *(uint32_t*)&hp;
        *(uint32_t*)(smraw + OFF_AL + (uint32_t)m * ASTRB + jp * 4)
            = *(uint32_t*)&lp;
    }
    // ---- stage ev slice ----
    for (int idx = t; idx < NH_PER * 128; idx += 512) {
        int hh = idx >> 7, m = idx & 127;
        int r = r0 + m;
        evs[hh * 128 + m] = (r < RTOT) ? ev[(size_t)r * HDIM + hbase + hh] : 0.f;
    }

    float acc[2][4][4];
#pragma unroll
    for (int ms = 0; ms < 2; ms++)
#pragma unroll
        for (int nt = 0; nt < 4; nt++)
#pragma unroll
            for (int q = 0; q < 4; q++) acc[ms][nt][q] = 0.f;

    int warpM = (w & 3) * 32;
    int warpN = (w >> 2) * 32;
    uint32_t aoff = (uint32_t)(warpM + (lane & 15)) * ASTRB + (uint32_t)(lane >> 4) * 16u;
    uint32_t boff = (uint32_t)(warpN + ((lane >> 4) & 1) * 8 + (lane & 7)) * ASTRB
                  + (uint32_t)((lane >> 3) & 1) * 16u;
    uint32_t AbH = base32 + OFF_AH + aoff;
    uint32_t AbL = base32 + OFF_AL + aoff;

    int rl0 = warpM + (lane >> 2);

    for (int hh = 0; hh < NH_PER; hh++) {
        int s = hh & 1;
        cp_wait0();
        __syncthreads();                 // stage-s B visible; readers of 1-s done
                                         // (also covers A-plane/evs visibility at hh=0)
        if (hh + 1 < NH_PER) {
            const char* sB = (const char*)(ENfp + (size_t)(hbase + hh + 1) * 16384);
            uint32_t dst = base32 + OFF_B + (uint32_t)(1 - s) * PLANE;
#pragma unroll
            for (int k = 0; k < 4; k++) {
                int f = t + 512 * k;
                uint32_t i = (uint32_t)(f >> 4), seg = (uint32_t)(f & 15);
                cp16(dst + i * ASTRB + seg * 16u, sB + (size_t)f * 16);
            }
            cp_commit();
        }

        uint32_t Bb = base32 + OFF_B + (uint32_t)s * PLANE + boff;

        float tt[2][4][4];
#pragma unroll
        for (int ms = 0; ms < 2; ms++)
#pragma unroll
            for (int nt = 0; nt < 4; nt++)
#pragma unroll
                for (int q = 0; q < 4; q++) tt[ms][nt][q] = 0.f;

#pragma unroll
        for (int ks = 0; ks < 8; ks++) {
            uint32_t ah0[4], ah1[4], al0[4], al1[4];
            ldsm4(ah0, AbH + ks * 32u);
            ldsm4(ah1, AbH + 4352u + ks * 32u);
            ldsm4(al0, AbL + ks * 32u);
            ldsm4(al1, AbL + 4352u + ks * 32u);
            uint32_t bh[2][4];
#pragma unroll
            for (int np = 0; np < 2; np++)
                ldsm4(bh[np], Bb + (uint32_t)np * 4352u + ks * 32u);
#pragma unroll
            for (int nt = 0; nt < 4; nt++) {
                uint32_t b0 = bh[nt >> 1][(nt & 1) * 2];
                uint32_t b1 = bh[nt >> 1][(nt & 1) * 2 + 1];
                mma_f16(tt[0][nt], ah0, b0, b1);   // AH*B
                mma_f16(tt[1][nt], ah1, b0, b1);
                mma_f16(tt[0][nt], al0, b0, b1);   // AL*B
                mma_f16(tt[1][nt], al1, b0, b1);
            }
        }

        const float* evh = evs + hh * 128;
        float ev0A = evh[rl0];
        float ev0B = evh[rl0 + 8];
        float ev1A = evh[rl0 + 16];
        float ev1B = evh[rl0 + 24];
#pragma unroll
        for (int nt = 0; nt < 4; nt++) {
            acc[0][nt][0] += ev0A * tt[0][nt][0];
            acc[0][nt][1] += ev0A * tt[0][nt][1];
            acc[0][nt][2] += ev0B * tt[0][nt][2];
            acc[0][nt][3] += ev0B * tt[0][nt][3];
            acc[1][nt][0] += ev1A * tt[1][nt][0];
            acc[1][nt][1] += ev1A * tt[1][nt][1];
            acc[1][nt][2] += ev1B * tt[1][nt][2];
            acc[1][nt][3] += ev1B * tt[1][nt][3];
        }
    }

    size_t obase = (size_t)blockIdx.y * RTOT * HDIM;
#pragma unroll
    for (int ms = 0; ms < 2; ms++) {
        int rA = r0 + warpM + ms * 16 + (lane >> 2);
        int rB = rA + 8;
#pragma unroll
        for (int nt = 0; nt < 4; nt++) {
            int col = warpN + nt * 8 + (lane & 3) * 2;
            if (rA < RTOT)
                *(float2*)&newp[obase + (size_t)rA * HDIM + col] =
                    make_float2(acc[ms][nt][0], acc[ms][nt][1]);
            if (rB < RTOT)
                *(float2*)&newp[obase + (size_t)rB * HDIM + col] =
                    make_float2(acc[ms][nt][2], acc[ms][nt][3]);
        }
    }
}

// out = (sum_z g_aggp[z] + node_state) * g_inv    (grid 250 exact)
__global__ void __launch_bounds__(256) k_fin(const float* __restrict__ ns,
                                             float* __restrict__ out) {
    const size_t STR = (size_t)BDIM * NDIM * HDIM / 4;
    size_t f = (size_t)blockIdx.x * 256 + threadIdx.x;
    const float4* p = (const float4*)g_aggp;
    float4 s = p[f];
#pragma unroll
    for (int z = 1; z < ZAGG; z++) {
        float4 v = p[z * STR + f];
        s.x += v.x; s.y += v.y; s.z += v.z; s.w += v.w;
    }
    float4 n4 = ((const float4*)ns)[f];
    float inv = g_inv[(f * 4) >> 7];
    float4 o;
    o.x = (s.x + n4.x) * inv;
    o.y = (s.y + n4.y) * inv;
    o.z = (s.z + n4.z) * inv;
    o.w = (s.w + n4.w) * inv;
    ((float4*)out)[f] = o;
}

// ---------------------------------------------------------------------------
extern "C" void kernel_launch(void* const* d_in, const int* in_sizes, int n_in,
                              void* d_out, int out_size) {
    const float* node_state   = (const float*)d_in[0];
    const float* edge_vec     = (const float*)d_in[1];
    const float* node2edge    = (const float*)d_in[2];
    const float* edge2node    = (const float*)d_in[3];
    const float* edge_network = (const float*)d_in[4];
    float* out = (float*)d_out;

    void* p_embp; cudaGetSymbolAddress(&p_embp, g_embp);
    void* p_newp; cudaGetSymbolAddress(&p_newp, g_newp);
    void* p_aggp; cudaGetSymbolAddress(&p_aggp, g_aggp);
    void* p_n2eH; cudaGetSymbolAddress(&p_n2eH, g_n2eH);
    void* p_n2eL; cudaGetSymbolAddress(&p_n2eL, g_n2eL);
    void* p_e2nH; cudaGetSymbolAddress(&p_e2nH, g_e2nH);
    void* p_e2nL; cudaGetSymbolAddress(&p_e2nL, g_e2nL);
    void* p_nsTH; cudaGetSymbolAddress(&p_nsTH, g_nsTH);
    void* p_nsTL; cudaGetSymbolAddress(&p_nsTL, g_nsTL);
    void* p_nwTH; cudaGetSymbolAddress(&p_nwTH, g_nwTH);
    void* p_nwTL; cudaGetSymbolAddress(&p_nwTL, g_nwTL);
    void* p_enf;  cudaGetSymbolAddress(&p_enf,  g_ENfp);

    cudaFuncSetAttribute(k_econv_tc, cudaFuncAttributeMaxDynamicSharedMemorySize,
                         SM_ECONV);
    cudaFuncSetAttribute(k_gemm_tc2, cudaFuncAttributeMaxDynamicSharedMemorySize,
                         SM_GEMM2);

    k_prep<<<HDIM, 256>>>(edge_network);
    k_splitrow<<<RTOT, 256>>>(node2edge, (unsigned short*)p_n2eH,
                              (unsigned short*)p_n2eL, NDIM, KP1, 0);
    k_splitrow<<<BDIM * NDIM, 256>>>(edge2node, (unsigned short*)p_e2nH,
                                     (unsigned short*)p_e2nL, EDIM, KP2, 1);
    k_trs<<<dim3(32, 4, BDIM), 256>>>(node_state);
    // n2e: (16,2,4) = 128 blocks
    k_gemm_tc2<<<dim3(16, BDIM, ZN2E), 512, SM_GEMM2>>>(
        (const unsigned short*)p_n2eH, (const unsigned short*)p_n2eL,
        (const unsigned short*)p_nsTH, (const unsigned short*)p_nsTL,
        (float*)p_embp, EDIM, KP1);
    // econv (fp16 2-term; A-build fuses split-K reduce of g_embp)
    k_econv_tc<<<dim3(32, HSPLIT), 512, SM_ECONV>>>(edge_vec,
                                                    (const unsigned short*)p_enf,
                                                    (float*)p_newp);
    // HSPLIT-reduce + transpose + split -> g_nwT planes
    k_nredT<<<dim3(64, 4, BDIM), 256>>>((const float*)p_newp);
    // agg: (8,2,8) = 128 blocks
    k_gemm_tc2<<<dim3(8, BDIM, ZAGG), 512, SM_GEMM2>>>(
        (const unsigned short*)p_e2nH, (const unsigned short*)p_e2nL,
        (const unsigned short*)p_nwTH, (const unsigned short*)p_nwTL,
        (float*)p_aggp, NDIM, KP2);
    k_fin<<<250, 256>>>(node_state, out);
}

// round 14
// speedup vs baseline: 1.9077x; 1.0656x over previous
#include <cuda_runtime.h>
#include <cuda_bf16.h>
#include <cuda_fp16.h>
#include <cstdint>

#define BDIM 2
#define NDIM 1000
#define EDIM 2000
#define HDIM 128
#define RTOT (BDIM * EDIM)          // 4000 flat rows

#define HSPLIT 4                    // h-splits for econv tensor kernel
#define NH_PER (HDIM / HSPLIT)      // 32 h per block

#define ZN2E 4                      // split-K for n2e tc-gemm (KP=1024 -> 256)
#define ZAGG 8                      // split-K for agg tc-gemm (KP=2048 -> 256)
#define KP1  1024                   // node2edge K=1000 padded
#define KP2  2048                   // edge2node K=2000 padded

// ---------------- scratch (device globals) ---------------------------------
__device__ float g_embp[(size_t)ZN2E * RTOT * HDIM];          // n2e partials
__device__ float g_newp[(size_t)HSPLIT * RTOT * HDIM];        // econv partials
__device__ float g_aggp[(size_t)ZAGG * BDIM * NDIM * HDIM];   // agg partials
__device__ float g_inv [(size_t)BDIM * NDIM];
// bf16 hi/lo operand planes (pre-split, K-padded) for glue GEMMs
__device__ unsigned short g_n2eH[(size_t)RTOT * KP1];
__device__ unsigned short g_n2eL[(size_t)RTOT * KP1];
__device__ unsigned short g_e2nH[(size_t)BDIM * NDIM * KP2];
__device__ unsigned short g_e2nL[(size_t)BDIM * NDIM * KP2];
__device__ unsigned short g_nsTH[(size_t)BDIM * HDIM * KP1];
__device__ unsigned short g_nsTL[(size_t)BDIM * HDIM * KP1];
__device__ unsigned short g_nwTH[(size_t)BDIM * HDIM * KP2];
__device__ unsigned short g_nwTL[(size_t)BDIM * HDIM * KP2];
// EN as single fp16 plane, plain [h][i][j] layout (econv B operand)
__device__ unsigned short g_ENfp[(size_t)HDIM * 16384];

// ---------------- helpers ---------------------------------------------------
__device__ __forceinline__ uint32_t smem_u32(const void* p) {
    uint32_t a;
    asm("{ .reg .u64 t; cvta.to.shared.u64 t, %1; cvt.u32.u64 %0, t; }"
        : "=r"(a) : "l"(p));
    return a;
}
__device__ __forceinline__ void ldsm4(uint32_t* r, uint32_t addr) {
    asm volatile("ldmatrix.sync.aligned.m8n8.x4.shared.b16 {%0,%1,%2,%3}, [%4];"
                 : "=r"(r[0]), "=r"(r[1]), "=r"(r[2]), "=r"(r[3]) : "r"(addr));
}
__device__ __forceinline__ void mma_bf16(float* d, const uint32_t* a,
                                         uint32_t b0, uint32_t b1) {
    asm volatile("mma.sync.aligned.m16n8k16.row.col.f32.bf16.bf16.f32 "
                 "{%0,%1,%2,%3}, {%4,%5,%6,%7}, {%8,%9}, {%0,%1,%2,%3};"
                 : "+f"(d[0]), "+f"(d[1]), "+f"(d[2]), "+f"(d[3])
                 : "r"(a[0]), "r"(a[1]), "r"(a[2]), "r"(a[3]), "r"(b0), "r"(b1));
}
__device__ __forceinline__ void mma_f16(float* d, const uint32_t* a,
                                        uint32_t b0, uint32_t b1) {
    asm volatile("mma.sync.aligned.m16n8k16.row.col.f32.f16.f16.f32 "
                 "{%0,%1,%2,%3}, {%4,%5,%6,%7}, {%8,%9}, {%0,%1,%2,%3};"
                 : "+f"(d[0]), "+f"(d[1]), "+f"(d[2]), "+f"(d[3])
                 : "r"(a[0]), "r"(a[1]), "r"(a[2]), "r"(a[3]), "r"(b0), "r"(b1));
}
__device__ __forceinline__ void cp16(uint32_t dst, const void* src) {
    asm volatile("cp.async.cg.shared.global [%0], [%1], 16;"
                 :: "r"(dst), "l"(src) : "memory");
}
__device__ __forceinline__ void cp_commit() {
    asm volatile("cp.async.commit_group;" ::: "memory");
}
__device__ __forceinline__ void cp_wait0() {
    asm volatile("cp.async.wait_group 0;" ::: "memory");
}
__device__ __forceinline__ void bf16_split(float v, unsigned short& h,
                                           unsigned short& l) {
    __nv_bfloat16 hb = __float2bfloat16(v);
    float hf = __bfloat162float(hb);
    __nv_bfloat16 lb = __float2bfloat16(v - hf);
    h = *(unsigned short*)&hb;
    l = *(unsigned short*)&lb;
}

// ---------------------------------------------------------------------------
// Fused prologue kernel: grid sections dispatch the 4 independent prep tasks
//   [0,128)                : EN -> fp16 plane
//   [128, 128+RTOT)        : node2edge -> bf16 hi/lo, KP1
//   [.., +BDIM*NDIM)       : edge2node -> bf16 hi/lo, KP2  (+ rowsum -> g_inv)
//   [.., +256)             : node_state -> transposed bf16 hi/lo, KP1
// ---------------------------------------------------------------------------
#define SEC0 128
#define SEC1 (SEC0 + RTOT)
#define SEC2 (SEC1 + BDIM * NDIM)
#define SEC3 (SEC2 + 256)

__global__ void __launch_bounds__(256) k_pre(const float* __restrict__ EN,
                                             const float* __restrict__ n2e,
                                             const float* __restrict__ e2n,
                                             const float* __restrict__ ns) {
    int bid = blockIdx.x;
    int t = threadIdx.x;

    if (bid < SEC0) {                        // EN -> fp16
        int h = bid;
        const float* src = EN + (size_t)h * 16384;
        unsigned short* dp = g_ENfp + (size_t)h * 16384;
        for (int idx = t; idx < 16384; idx += 256) {
            __half hv = __float2half_rn(src[idx]);
            dp[idx] = *(unsigned short*)&hv;
        }
        return;
    }
    if (bid < SEC2) {                        // row-wise splits
        int is2 = (bid >= SEC1);
        int row = bid - (is2 ? SEC1 : SEC0);
        int K    = is2 ? EDIM : NDIM;
        int KPAD = is2 ? KP2 : KP1;
        const float* src = (is2 ? e2n : n2e) + (size_t)row * K;
        unsigned short* dh = (is2 ? g_e2nH : g_n2eH) + (size_t)row * KPAD;
        unsigned short* dl = (is2 ? g_e2nL : g_n2eL) + (size_t)row * KPAD;
        __shared__ float red[256];
        float sum = 0.f;
        for (int idx = t; idx < KPAD; idx += 256) {
            float v = (idx < K) ? src[idx] : 0.f;
            sum += v;
            unsigned short h, l;
            bf16_split(v, h, l);
            dh[idx] = h; dl[idx] = l;
        }
        if (is2) {
            red[t] = sum;
            __syncthreads();
            for (int o = 128; o > 0; o >>= 1) {
                if (t < o) red[t] += red[t + o];
                __syncthreads();
            }
            if (t == 0) g_inv[row] = 1.f / (1.f + red[0]);
        }
        return;
    }
    {                                        // node_state transpose+split
        int idx = bid - SEC2;                // 0..255  (32 x 4 x BDIM)
        int xb = idx & 31, yb = (idx >> 5) & 3, b = idx >> 7;
        __shared__ float tile[32][33];
        int n0 = xb * 32, h0 = yb * 32;
        int tx = t & 31, ty = t >> 5;
        for (int rr = ty; rr < 32; rr += 8) {
            int n = n0 + rr;
            tile[rr][tx] = (n < NDIM)
                ? ns[((size_t)b * NDIM + n) * HDIM + h0 + tx] : 0.f;
        }
        __syncthreads();
        for (int cc = ty; cc < 32; cc += 8) {
            int h = h0 + cc, n = n0 + tx;    // n < 1024 = KP1 always
            unsigned short hh, ll;
            bf16_split(tile[tx][cc], hh, ll);
            size_t o = ((size_t)b * HDIM + h) * KP1 + n;
            g_nsTH[o] = hh; g_nsTL[o] = ll;
        }
    }
}

// ---------------------------------------------------------------------------
// HSPLIT-reduce + transpose + split: g_nwT*[b][i][KP2] from newp partials
// grid (64, 4, BDIM) -> e tiles cover 2048 = KP2 (zero-padded past EDIM)
// ---------------------------------------------------------------------------
__global__ void __launch_bounds__(256) k_nredT(const float* __restrict__ newp) {
    __shared__ float tile[32][33];
    int b  = blockIdx.z;
    int e0 = blockIdx.x * 32, i0 = blockIdx.y * 32;
    int tx = threadIdx.x & 31, ty = threadIdx.x >> 5;
    for (int rr = ty; rr < 32; rr += 8) {
        int e = e0 + rr;
        float s = 0.f;
        if (e < EDIM) {
            size_t base = ((size_t)b * EDIM + e) * HDIM + i0 + tx;
#pragma unroll
            for (int z = 0; z < HSPLIT; z++)
                s += newp[(size_t)z * RTOT * HDIM + base];
        }
        tile[rr][tx] = s;
    }
    __syncthreads();
    for (int cc = ty; cc < 32; cc += 8) {
        int i = i0 + cc, e = e0 + tx;           // e < 2048 = KP2 always
        unsigned short hh, ll;
        bf16_split(tile[tx][cc], hh, ll);
        size_t o = ((size_t)b * HDIM + i) * KP2 + e;
        g_nwTH[o] = hh; g_nwTL[o] = ll;
    }
}

// ---------------------------------------------------------------------------
// Tensor-core split-K GEMM on PRE-SPLIT bf16 planes (unchanged from r13).
// ---------------------------------------------------------------------------
#define TSTR 144u                   // (64 bf16 = 128B) + 16B pad
#define PL2  18432u                 // plane: 128*144
#define STG2 73728u                 // stage: 4 planes (AH, AL, BH, BL)
#define SM_GEMM2 147456u            // 2 stages

__global__ void __launch_bounds__(512) k_gemm_tc2(const unsigned short* __restrict__ Ah,
                                                  const unsigned short* __restrict__ Al,
                                                  const unsigned short* __restrict__ Bh,
                                                  const unsigned short* __restrict__ Bl,
                                                  float* __restrict__ out,
                                                  int ROWS, int KPAD) {
    extern __shared__ char smraw[];
    uint32_t base32 = smem_u32(smraw);

    int t = threadIdx.x;
    int lane = t & 31, w = t >> 5;
    int b  = blockIdx.y;
    int z  = blockIdx.z;
    int r0 = blockIdx.x * 128;

    const unsigned short* planes[4] = { Ah, Al, Bh, Bl };

    auto copy_kc = [&](int kc, int s) {
        int k0 = z * 256 + kc * 64;
#pragma unroll
        for (int q = 0; q < 8; q++) {
            int f = t + 512 * q;            // 0..4095
            int pl = f >> 10;
            int idx = f & 1023;
            int row = idx >> 3, seg = idx & 7;
            uint32_t dst = base32 + (uint32_t)s * STG2 + (uint32_t)pl * PL2
                         + (uint32_t)row * TSTR + (uint32_t)seg * 16u;
            if (pl < 2) {                   // A planes: guard ragged M
                int rg = r0 + row;
                if (rg < ROWS) {
                    cp16(dst, planes[pl] + ((size_t)b * ROWS + rg) * KPAD
                              + k0 + seg * 8);
                } else {
                    *(uint4*)(smraw + (uint32_t)s * STG2 + (uint32_t)pl * PL2
                              + (uint32_t)row * TSTR + (uint32_t)seg * 16u)
                        = make_uint4(0, 0, 0, 0);
                }
            } else {                        // B planes: 128 rows exact
                cp16(dst, planes[pl] + ((size_t)b * HDIM + row) * KPAD
                          + k0 + seg * 8);
            }
        }
        cp_commit();
    };

    float acc[2][4][4];
#pragma unroll
    for (int ms = 0; ms < 2; ms++)
#pragma unroll
        for (int nt = 0; nt < 4; nt++)
#pragma unroll
            for (int q = 0; q < 4; q++) acc[ms][nt][q] = 0.f;

    int warpM = (w & 3) * 32;
    int warpN = (w >> 2) * 32;
    uint32_t aoff = (uint32_t)(warpM + (lane & 15)) * TSTR + (uint32_t)(lane >> 4) * 16u;
    uint32_t boff = (uint32_t)(warpN + ((lane >> 4) & 1) * 8 + (lane & 7)) * TSTR
                  + (uint32_t)((lane >> 3) & 1) * 16u;

    copy_kc(0, 0);                          // prologue

    for (int kc = 0; kc < 4; kc++) {
        int s = kc & 1;
        cp_wait0();
        __syncthreads();
        if (kc + 1 < 4) copy_kc(kc + 1, 1 - s);

        uint32_t AbH = base32 + (uint32_t)s * STG2 + aoff;
        uint32_t AbL = AbH + PL2;
        uint32_t BbH = base32 + (uint32_t)s * STG2 + 2u * PL2 + boff;
        uint32_t BbL = BbH + PL2;

#pragma unroll
        for (int ks = 0; ks < 4; ks++) {
            uint32_t ah0[4], ah1[4], al0[4], al1[4];
            ldsm4(ah0, AbH + ks * 32u);
            ldsm4(ah1, AbH + 2304u + ks * 32u);      // +16 rows
            ldsm4(al0, AbL + ks * 32u);
            ldsm4(al1, AbL + 2304u + ks * 32u);
            uint32_t bh[2][4], bl[2][4];
#pragma unroll
            for (int np = 0; np < 2; np++) {
                ldsm4(bh[np], BbH + (uint32_t)np * 2304u + ks * 32u);
                ldsm4(bl[np], BbL + (uint32_t)np * 2304u + ks * 32u);
            }
#pragma unroll
            for (int nt = 0; nt < 4; nt++) {
                uint32_t b0h = bh[nt >> 1][(nt & 1) * 2];
                uint32_t b1h = bh[nt >> 1][(nt & 1) * 2 + 1];
                uint32_t b0l = bl[nt >> 1][(nt & 1) * 2];
                uint32_t b1l = bl[nt >> 1][(nt & 1) * 2 + 1];
                mma_bf16(acc[0][nt], ah0, b0h, b1h);   // AH*BH
                mma_bf16(acc[1][nt], ah1, b0h, b1h);
                mma_bf16(acc[0][nt], ah0, b0l, b1l);   // AH*BL
                mma_bf16(acc[1][nt], ah1, b0l, b1l);
                mma_bf16(acc[0][nt], al0, b0h, b1h);   // AL*BH
                mma_bf16(acc[1][nt], al1, b0h, b1h);
            }
        }
        __syncthreads();
    }

#pragma unroll
    for (int ms = 0; ms < 2; ms++) {
        int rA = r0 + warpM + ms * 16 + (lane >> 2);
        int rB = rA + 8;
#pragma unroll
        for (int nt = 0; nt < 4; nt++) {
            int col = warpN + nt * 8 + (lane & 3) * 2;
            if (rA < ROWS)
                *(float2*)&out[((size_t)z * BDIM * ROWS + (size_t)b * ROWS + rA)
                               * HDIM + col] =
                    make_float2(acc[ms][nt][0], acc[ms][nt][1]);
            if (rB < ROWS)
                *(float2*)&out[((size_t)z * BDIM * ROWS + (size_t)b * ROWS + rB)
                               * HDIM + col] =
                    make_float2(acc[ms][nt][2], acc[ms][nt][3]);
        }
    }
}

// ---------------------------------------------------------------------------
// Tensor-core econv, fp16 2-term, 256 threads / 8 warps, warp tile 32x64:
// fewer ldsm per mma (8 per 32 vs 6 per 16) -> smem crossbar off critical path.
// A = emb split hi/lo fp16 (h-invariant smem), B = EN fp16 (cp.async dbl-buf).
// A-build fuses the split-K reduce of g_embp.
// ---------------------------------------------------------------------------
#define ASTRB 272u
#define PLANE 34816u
#define OFF_AH 0u
#define OFF_AL 34816u
#define OFF_B  69632u                // stage s at OFF_B + s*34816 (single plane)
#define OFF_EV 139264u               // float [NH_PER][128]
#define SM_ECONV 155648u

__global__ void __launch_bounds__(256) k_econv_tc(const float* __restrict__ ev,
                                                  const unsigned short* __restrict__ ENfp,
                                                  float* __restrict__ newp) {
    extern __shared__ char smraw[];
    uint32_t base32 = smem_u32(smraw);
    float* evs = (float*)(smraw + OFF_EV);

    int t = threadIdx.x;
    int lane = t & 31, w = t >> 5;
    int r0 = blockIdx.x * 128;
    int hbase = blockIdx.y * NH_PER;

    // ---- issue stage-0 B copy immediately (overlaps A build) ----
    {
        const char* sB = (const char*)(ENfp + (size_t)hbase * 16384);
        uint32_t dst = base32 + OFF_B;
#pragma unroll
        for (int k = 0; k < 8; k++) {
            int f = t + 256 * k;
            uint32_t i = (uint32_t)(f >> 4), seg = (uint32_t)(f & 15);
            cp16(dst + i * ASTRB + seg * 16u, sB + (size_t)f * 16);
        }
        cp_commit();
    }

    // ---- build A planes: emb = sum_z embp[z], split hi/lo fp16 ----
#pragma unroll 4
    for (int k = 0; k < 32; k++) {
        int p = t + 256 * k;
        int m = p >> 6, jp = p & 63;
        int r = r0 + m;
        float ex = 0.f, ey = 0.f;
        if (r < RTOT) {
#pragma unroll
            for (int z = 0; z < ZN2E; z++) {
                float2 v = *(const float2*)&g_embp[((size_t)z * RTOT + r) * HDIM
                                                   + jp * 2];
                ex += v.x; ey += v.y;
            }
        }
        __half hx = __float2half_rn(ex), hy = __float2half_rn(ey);
        __half lx = __float2half_rn(ex - __half2float(hx));
        __half ly = __float2half_rn(ey - __half2float(hy));
        __half2 hp = __halves2half2(hx, hy);
        __half2 lp = __halves2half2(lx, ly);
        *(uint32_t*)(smraw + OFF_AH + (uint32_t)m * ASTRB + jp * 4)
            = *(uint32_t*)&hp;
        *(uint32_t*)(smraw + OFF_AL + (uint32_t)m * ASTRB + jp * 4)
            = *(uint32_t*)&lp;
    }
    // ---- stage ev slice ----
    for (int idx = t; idx < NH_PER * 128; idx += 256) {
        int hh = idx >> 7, m = idx & 127;
        int r = r0 + m;
        evs[hh * 128 + m] = (r < RTOT) ? ev[(size_t)r * HDIM + hbase + hh] : 0.f;
    }

    float acc[2][8][4];
#pragma unroll
    for (int ms = 0; ms < 2; ms++)
#pragma unroll
        for (int nt = 0; nt < 8; nt++)
#pragma unroll
            for (int q = 0; q < 4; q++) acc[ms][nt][q] = 0.f;

    int warpM = (w & 3) * 32;
    int warpN = (w >> 2) * 64;
    uint32_t aoff = (uint32_t)(warpM + (lane & 15)) * ASTRB + (uint32_t)(lane >> 4) * 16u;
    uint32_t boff = (uint32_t)(warpN + ((lane >> 4) & 1) * 8 + (lane & 7)) * ASTRB
                  + (uint32_t)((lane >> 3) & 1) * 16u;
    uint32_t AbH = base32 + OFF_AH + aoff;
    uint32_t AbL = base32 + OFF_AL + aoff;

    int rl0 = warpM + (lane >> 2);

    for (int hh = 0; hh < NH_PER; hh++) {
        int s = hh & 1;
        cp_wait0();
        __syncthreads();                 // stage-s B visible; readers of 1-s done
                                         // (also covers A-plane/evs at hh=0)
        if (hh + 1 < NH_PER) {
            const char* sB = (const char*)(ENfp + (size_t)(hbase + hh + 1) * 16384);
            uint32_t dst = base32 + OFF_B + (uint32_t)(1 - s) * PLANE;
#pragma unroll
            for (int k = 0; k < 8; k++) {
                int f = t + 256 * k;
                uint32_t i = (uint32_t)(f >> 4), seg = (uint32_t)(f & 15);
                cp16(dst + i * ASTRB + seg * 16u, sB + (size_t)f * 16);
            }
            cp_commit();
        }

        uint32_t Bb = base32 + OFF_B + (uint32_t)s * PLANE + boff;

        float tt[2][8][4];
#pragma unroll
        for (int ms = 0; ms < 2; ms++)
#pragma unroll
            for (int nt = 0; nt < 8; nt++)
#pragma unroll
                for (int q = 0; q < 4; q++) tt[ms][nt][q] = 0.f;

#pragma unroll
        for (int ks = 0; ks < 8; ks++) {
            uint32_t ah0[4], ah1[4], al0[4], al1[4];
            ldsm4(ah0, AbH + ks * 32u);
            ldsm4(ah1, AbH + 4352u + ks * 32u);
            ldsm4(al0, AbL + ks * 32u);
            ldsm4(al1, AbL + 4352u + ks * 32u);
            uint32_t bh[4][4];
#pragma unroll
            for (int np = 0; np < 4; np++)
                ldsm4(bh[np], Bb + (uint32_t)np * 4352u + ks * 32u);
#pragma unroll
            for (int nt = 0; nt < 8; nt++) {
                uint32_t b0 = bh[nt >> 1][(nt & 1) * 2];
                uint32_t b1 = bh[nt >> 1][(nt & 1) * 2 + 1];
                mma_f16(tt[0][nt], ah0, b0, b1);   // AH*B
                mma_f16(tt[1][nt], ah1, b0, b1);
                mma_f16(tt[0][nt], al0, b0, b1);   // AL*B
                mma_f16(tt[1][nt], al1, b0, b1);
            }
        }

        const float* evh = evs + hh * 128;
        float ev0A = evh[rl0];
        float ev0B = evh[rl0 + 8];
        float ev1A = evh[rl0 + 16];
        float ev1B = evh[rl0 + 24];
#pragma unroll
        for (int nt = 0; nt < 8; nt++) {
            acc[0][nt][0] += ev0A * tt[0][nt][0];
            acc[0][nt][1] += ev0A * tt[0][nt][1];
            acc[0][nt][2] += ev0B * tt[0][nt][2];
            acc[0][nt][3] += ev0B * tt[0][nt][3];
            acc[1][nt][0] += ev1A * tt[1][nt][0];
            acc[1][nt][1] += ev1A * tt[1][nt][1];
            acc[1][nt][2] += ev1B * tt[1][nt][2];
            acc[1][nt][3] += ev1B * tt[1][nt][3];
        }
    }

    size_t obase = (size_t)blockIdx.y * RTOT * HDIM;
#pragma unroll
    for (int ms = 0; ms < 2; ms++) {
        int rA = r0 + warpM + ms * 16 + (lane >> 2);
        int rB = rA + 8;
#pragma unroll
        for (int nt = 0; nt < 8; nt++) {
            int col = warpN + nt * 8 + (lane & 3) * 2;
            if (rA < RTOT)
                *(float2*)&newp[obase + (size_t)rA * HDIM + col] =
                    make_float2(acc[ms][nt][0], acc[ms][nt][1]);
            if (rB < RTOT)
                *(float2*)&newp[obase + (size_t)rB * HDIM + col] =
                    make_float2(acc[ms][nt][2], acc[ms][nt][3]);
        }
    }
}

// out = (sum_z g_aggp[z] + node_state) * g_inv    (grid 250 exact)
__global__ void __launch_bounds__(256) k_fin(const float* __restrict__ ns,
                                             float* __restrict__ out) {
    const size_t STR = (size_t)BDIM * NDIM * HDIM / 4;
    size_t f = (size_t)blockIdx.x * 256 + threadIdx.x;
    const float4* p = (const float4*)g_aggp;
    float4 s = p[f];
#pragma unroll
    for (int z = 1; z < ZAGG; z++) {
        float4 v = p[z * STR + f];
        s.x += v.x; s.y += v.y; s.z += v.z; s.w += v.w;
    }
    float4 n4 = ((const float4*)ns)[f];
    float inv = g_inv[(f * 4) >> 7];
    float4 o;
    o.x = (s.x + n4.x) * inv;
    o.y = (s.y + n4.y) * inv;
    o.z = (s.z + n4.z) * inv;
    o.w = (s.w + n4.w) * inv;
    ((float4*)out)[f] = o;
}

// ---------------------------------------------------------------------------
extern "C" void kernel_launch(void* const* d_in, const int* in_sizes, int n_in,
                              void* d_out, int out_size) {
    const float* node_state   = (const float*)d_in[0];
    const float* edge_vec     = (const float*)d_in[1];
    const float* node2edge    = (const float*)d_in[2];
    const float* edge2node    = (const float*)d_in[3];
    const float* edge_network = (const float*)d_in[4];
    float* out = (float*)d_out;

    void* p_embp; cudaGetSymbolAddress(&p_embp, g_embp);
    void* p_newp; cudaGetSymbolAddress(&p_newp, g_newp);
    void* p_aggp; cudaGetSymbolAddress(&p_aggp, g_aggp);
    void* p_n2eH; cudaGetSymbolAddress(&p_n2eH, g_n2eH);
    void* p_n2eL; cudaGetSymbolAddress(&p_n2eL, g_n2eL);
    void* p_e2nH; cudaGetSymbolAddress(&p_e2nH, g_e2nH);
    void* p_e2nL; cudaGetSymbolAddress(&p_e2nL, g_e2nL);
    void* p_nsTH; cudaGetSymbolAddress(&p_nsTH, g_nsTH);
    void* p_nsTL; cudaGetSymbolAddress(&p_nsTL, g_nsTL);
    void* p_nwTH; cudaGetSymbolAddress(&p_nwTH, g_nwTH);
    void* p_nwTL; cudaGetSymbolAddress(&p_nwTL, g_nwTL);
    void* p_enf;  cudaGetSymbolAddress(&p_enf,  g_ENfp);

    cudaFuncSetAttribute(k_econv_tc, cudaFuncAttributeMaxDynamicSharedMemorySize,
                         SM_ECONV);
    cudaFuncSetAttribute(k_gemm_tc2, cudaFuncAttributeMaxDynamicSharedMemorySize,
                         SM_GEMM2);

    // fused prologue: EN prep + both row splits (+norm) + node_state transpose
    k_pre<<<SEC3, 256>>>(edge_network, node2edge, edge2node, node_state);
    // n2e: (16,2,4) = 128 blocks
    k_gemm_tc2<<<dim3(16, BDIM, ZN2E), 512, SM_GEMM2>>>(
        (const unsigned short*)p_n2eH, (const unsigned short*)p_n2eL,
        (const unsigned short*)p_nsTH, (const unsigned short*)p_nsTL,
        (float*)p_embp, EDIM, KP1);
    // econv (fp16 2-term, 8 warps x 32x64 tiles)
    k_econv_tc<<<dim3(32, HSPLIT), 256, SM_ECONV>>>(edge_vec,
                                                    (const unsigned short*)p_enf,
                                                    (float*)p_newp);
    // HSPLIT-reduce + transpose + split -> g_nwT planes
    k_nredT<<<dim3(64, 4, BDIM), 256>>>((const float*)p_newp);
    // agg: (8,2,8) = 128 blocks
    k_gemm_tc2<<<dim3(8, BDIM, ZAGG), 512, SM_GEMM2>>>(
        (const unsigned short*)p_e2nH, (const unsigned short*)p_e2nL,
        (const unsigned short*)p_nwTH, (const unsigned short*)p_nwTL,
        (float*)p_aggp, NDIM, KP2);
    k_fin<<<250, 256>>>(node_state, out);
}

// round 15
// speedup vs baseline: 2.4777x; 1.2988x over previous
#include <cuda_runtime.h>
#include <cuda_bf16.h>
#include <cuda_fp16.h>
#include <cstdint>

#define BDIM 2
#define NDIM 1000
#define EDIM 2000
#define HDIM 128
#define RTOT (BDIM * EDIM)          // 4000 flat rows

#define HSPLIT 4                    // h-splits for econv tensor kernel
#define NH_PER (HDIM / HSPLIT)      // 32 h per block

#define ZN2E 4                      // split-K for n2e tc-gemm (KP=1024 -> 256)
#define ZAGG 8                      // split-K for agg tc-gemm (KP=2048 -> 256)
#define KP1  1024                   // node2edge K=1000 padded
#define KP2  2048                   // edge2node K=2000 padded

// ---------------- scratch (device globals) ---------------------------------
__device__ float g_embp[(size_t)ZN2E * RTOT * HDIM];          // n2e partials
__device__ float g_newp[(size_t)HSPLIT * RTOT * HDIM];        // econv partials
__device__ float g_aggp[(size_t)ZAGG * BDIM * NDIM * HDIM];   // agg partials
__device__ float g_inv [(size_t)BDIM * NDIM];
// bf16 hi/lo operand planes (pre-split, K-padded) for glue GEMMs
__device__ unsigned short g_n2eH[(size_t)RTOT * KP1];
__device__ unsigned short g_n2eL[(size_t)RTOT * KP1];
__device__ unsigned short g_e2nH[(size_t)BDIM * NDIM * KP2];
__device__ unsigned short g_e2nL[(size_t)BDIM * NDIM * KP2];
__device__ unsigned short g_nsTH[(size_t)BDIM * HDIM * KP1];
__device__ unsigned short g_nsTL[(size_t)BDIM * HDIM * KP1];
__device__ unsigned short g_nwTH[(size_t)BDIM * HDIM * KP2];
__device__ unsigned short g_nwTL[(size_t)BDIM * HDIM * KP2];
// EN as single fp16 plane, plain [h][i][j] layout (econv B operand)
__device__ unsigned short g_ENfp[(size_t)HDIM * 16384];

// ---------------- helpers ---------------------------------------------------
__device__ __forceinline__ uint32_t smem_u32(const void* p) {
    uint32_t a;
    asm("{ .reg .u64 t; cvta.to.shared.u64 t, %1; cvt.u32.u64 %0, t; }"
        : "=r"(a) : "l"(p));
    return a;
}
__device__ __forceinline__ void ldsm4(uint32_t* r, uint32_t addr) {
    asm volatile("ldmatrix.sync.aligned.m8n8.x4.shared.b16 {%0,%1,%2,%3}, [%4];"
                 : "=r"(r[0]), "=r"(r[1]), "=r"(r[2]), "=r"(r[3]) : "r"(addr));
}
__device__ __forceinline__ void mma_bf16(float* d, const uint32_t* a,
                                         uint32_t b0, uint32_t b1) {
    asm volatile("mma.sync.aligned.m16n8k16.row.col.f32.bf16.bf16.f32 "
                 "{%0,%1,%2,%3}, {%4,%5,%6,%7}, {%8,%9}, {%0,%1,%2,%3};"
                 : "+f"(d[0]), "+f"(d[1]), "+f"(d[2]), "+f"(d[3])
                 : "r"(a[0]), "r"(a[1]), "r"(a[2]), "r"(a[3]), "r"(b0), "r"(b1));
}
__device__ __forceinline__ void mma_f16(float* d, const uint32_t* a,
                                        uint32_t b0, uint32_t b1) {
    asm volatile("mma.sync.aligned.m16n8k16.row.col.f32.f16.f16.f32 "
                 "{%0,%1,%2,%3}, {%4,%5,%6,%7}, {%8,%9}, {%0,%1,%2,%3};"
                 : "+f"(d[0]), "+f"(d[1]), "+f"(d[2]), "+f"(d[3])
                 : "r"(a[0]), "r"(a[1]), "r"(a[2]), "r"(a[3]), "r"(b0), "r"(b1));
}
__device__ __forceinline__ void cp16(uint32_t dst, const void* src) {
    asm volatile("cp.async.cg.shared.global [%0], [%1], 16;"
                 :: "r"(dst), "l"(src) : "memory");
}
__device__ __forceinline__ void cp_commit() {
    asm volatile("cp.async.commit_group;" ::: "memory");
}
__device__ __forceinline__ void cp_wait0() {
    asm volatile("cp.async.wait_group 0;" ::: "memory");
}
__device__ __forceinline__ void bf16_split(float v, unsigned short& h,
                                           unsigned short& l) {
    __nv_bfloat16 hb = __float2bfloat16(v);
    float hf = __bfloat162float(hb);
    __nv_bfloat16 lb = __float2bfloat16(v - hf);
    h = *(unsigned short*)&hb;
    l = *(unsigned short*)&lb;
}

// ---------------------------------------------------------------------------
// Fused prologue kernel: grid sections dispatch the 4 independent prep tasks
//   [0,128)                : EN -> fp16 plane
//   [128, 128+RTOT)        : node2edge -> bf16 hi/lo, KP1
//   [.., +BDIM*NDIM)       : edge2node -> bf16 hi/lo, KP2  (+ rowsum -> g_inv)
//   [.., +256)             : node_state -> transposed bf16 hi/lo, KP1
// ---------------------------------------------------------------------------
#define SEC0 128
#define SEC1 (SEC0 + RTOT)
#define SEC2 (SEC1 + BDIM * NDIM)
#define SEC3 (SEC2 + 256)

__global__ void __launch_bounds__(256) k_pre(const float* __restrict__ EN,
                                             const float* __restrict__ n2e,
                                             const float* __restrict__ e2n,
                                             const float* __restrict__ ns) {
    int bid = blockIdx.x;
    int t = threadIdx.x;

    if (bid < SEC0) {                        // EN -> fp16
        int h = bid;
        const float* src = EN + (size_t)h * 16384;
        unsigned short* dp = g_ENfp + (size_t)h * 16384;
        for (int idx = t; idx < 16384; idx += 256) {
            __half hv = __float2half_rn(src[idx]);
            dp[idx] = *(unsigned short*)&hv;
        }
        return;
    }
    if (bid < SEC2) {                        // row-wise splits
        int is2 = (bid >= SEC1);
        int row = bid - (is2 ? SEC1 : SEC0);
        int K    = is2 ? EDIM : NDIM;
        int KPAD = is2 ? KP2 : KP1;
        const float* src = (is2 ? e2n : n2e) + (size_t)row * K;
        unsigned short* dh = (is2 ? g_e2nH : g_n2eH) + (size_t)row * KPAD;
        unsigned short* dl = (is2 ? g_e2nL : g_n2eL) + (size_t)row * KPAD;
        __shared__ float red[256];
        float sum = 0.f;
        for (int idx = t; idx < KPAD; idx += 256) {
            float v = (idx < K) ? src[idx] : 0.f;
            sum += v;
            unsigned short h, l;
            bf16_split(v, h, l);
            dh[idx] = h; dl[idx] = l;
        }
        if (is2) {
            red[t] = sum;
            __syncthreads();
            for (int o = 128; o > 0; o >>= 1) {
                if (t < o) red[t] += red[t + o];
                __syncthreads();
            }
            if (t == 0) g_inv[row] = 1.f / (1.f + red[0]);
        }
        return;
    }
    {                                        // node_state transpose+split
        int idx = bid - SEC2;                // 0..255  (32 x 4 x BDIM)
        int xb = idx & 31, yb = (idx >> 5) & 3, b = idx >> 7;
        __shared__ float tile[32][33];
        int n0 = xb * 32, h0 = yb * 32;
        int tx = t & 31, ty = t >> 5;
        for (int rr = ty; rr < 32; rr += 8) {
            int n = n0 + rr;
            tile[rr][tx] = (n < NDIM)
                ? ns[((size_t)b * NDIM + n) * HDIM + h0 + tx] : 0.f;
        }
        __syncthreads();
        for (int cc = ty; cc < 32; cc += 8) {
            int h = h0 + cc, n = n0 + tx;    // n < 1024 = KP1 always
            unsigned short hh, ll;
            bf16_split(tile[tx][cc], hh, ll);
            size_t o = ((size_t)b * HDIM + h) * KP1 + n;
            g_nsTH[o] = hh; g_nsTL[o] = ll;
        }
    }
}

// ---------------------------------------------------------------------------
// HSPLIT-reduce + transpose + split: g_nwT*[b][i][KP2] from newp partials
// grid (64, 4, BDIM) -> e tiles cover 2048 = KP2 (zero-padded past EDIM)
// ---------------------------------------------------------------------------
__global__ void __launch_bounds__(256) k_nredT(const float* __restrict__ newp) {
    __shared__ float tile[32][33];
    int b  = blockIdx.z;
    int e0 = blockIdx.x * 32, i0 = blockIdx.y * 32;
    int tx = threadIdx.x & 31, ty = threadIdx.x >> 5;
    for (int rr = ty; rr < 32; rr += 8) {
        int e = e0 + rr;
        float s = 0.f;
        if (e < EDIM) {
            size_t base = ((size_t)b * EDIM + e) * HDIM + i0 + tx;
#pragma unroll
            for (int z = 0; z < HSPLIT; z++)
                s += newp[(size_t)z * RTOT * HDIM + base];
        }
        tile[rr][tx] = s;
    }
    __syncthreads();
    for (int cc = ty; cc < 32; cc += 8) {
        int i = i0 + cc, e = e0 + tx;           // e < 2048 = KP2 always
        unsigned short hh, ll;
        bf16_split(tile[tx][cc], hh, ll);
        size_t o = ((size_t)b * HDIM + i) * KP2 + e;
        g_nwTH[o] = hh; g_nwTL[o] = ll;
    }
}

// ---------------------------------------------------------------------------
// Tensor-core split-K GEMM on PRE-SPLIT bf16 planes (unchanged from r13/14).
// ---------------------------------------------------------------------------
#define TSTR 144u                   // (64 bf16 = 128B) + 16B pad
#define PL2  18432u                 // plane: 128*144
#define STG2 73728u                 // stage: 4 planes (AH, AL, BH, BL)
#define SM_GEMM2 147456u            // 2 stages

__global__ void __launch_bounds__(512) k_gemm_tc2(const unsigned short* __restrict__ Ah,
                                                  const unsigned short* __restrict__ Al,
                                                  const unsigned short* __restrict__ Bh,
                                                  const unsigned short* __restrict__ Bl,
                                                  float* __restrict__ out,
                                                  int ROWS, int KPAD) {
    extern __shared__ char smraw[];
    uint32_t base32 = smem_u32(smraw);

    int t = threadIdx.x;
    int lane = t & 31, w = t >> 5;
    int b  = blockIdx.y;
    int z  = blockIdx.z;
    int r0 = blockIdx.x * 128;

    const unsigned short* planes[4] = { Ah, Al, Bh, Bl };

    auto copy_kc = [&](int kc, int s) {
        int k0 = z * 256 + kc * 64;
#pragma unroll
        for (int q = 0; q < 8; q++) {
            int f = t + 512 * q;            // 0..4095
            int pl = f >> 10;
            int idx = f & 1023;
            int row = idx >> 3, seg = idx & 7;
            uint32_t dst = base32 + (uint32_t)s * STG2 + (uint32_t)pl * PL2
                         + (uint32_t)row * TSTR + (uint32_t)seg * 16u;
            if (pl < 2) {                   // A planes: guard ragged M
                int rg = r0 + row;
                if (rg < ROWS) {
                    cp16(dst, planes[pl] + ((size_t)b * ROWS + rg) * KPAD
                              + k0 + seg * 8);
                } else {
                    *(uint4*)(smraw + (uint32_t)s * STG2 + (uint32_t)pl * PL2
                              + (uint32_t)row * TSTR + (uint32_t)seg * 16u)
                        = make_uint4(0, 0, 0, 0);
                }
            } else {                        // B planes: 128 rows exact
                cp16(dst, planes[pl] + ((size_t)b * HDIM + row) * KPAD
                          + k0 + seg * 8);
            }
        }
        cp_commit();
    };

    float acc[2][4][4];
#pragma unroll
    for (int ms = 0; ms < 2; ms++)
#pragma unroll
        for (int nt = 0; nt < 4; nt++)
#pragma unroll
            for (int q = 0; q < 4; q++) acc[ms][nt][q] = 0.f;

    int warpM = (w & 3) * 32;
    int warpN = (w >> 2) * 32;
    uint32_t aoff = (uint32_t)(warpM + (lane & 15)) * TSTR + (uint32_t)(lane >> 4) * 16u;
    uint32_t boff = (uint32_t)(warpN + ((lane >> 4) & 1) * 8 + (lane & 7)) * TSTR
                  + (uint32_t)((lane >> 3) & 1) * 16u;

    copy_kc(0, 0);                          // prologue

    for (int kc = 0; kc < 4; kc++) {
        int s = kc & 1;
        cp_wait0();
        __syncthreads();
        if (kc + 1 < 4) copy_kc(kc + 1, 1 - s);

        uint32_t AbH = base32 + (uint32_t)s * STG2 + aoff;
        uint32_t AbL = AbH + PL2;
        uint32_t BbH = base32 + (uint32_t)s * STG2 + 2u * PL2 + boff;
        uint32_t BbL = BbH + PL2;

#pragma unroll
        for (int ks = 0; ks < 4; ks++) {
            uint32_t ah0[4], ah1[4], al0[4], al1[4];
            ldsm4(ah0, AbH + ks * 32u);
            ldsm4(ah1, AbH + 2304u + ks * 32u);      // +16 rows
            ldsm4(al0, AbL + ks * 32u);
            ldsm4(al1, AbL + 2304u + ks * 32u);
            uint32_t bh[2][4], bl[2][4];
#pragma unroll
            for (int np = 0; np < 2; np++) {
                ldsm4(bh[np], BbH + (uint32_t)np * 2304u + ks * 32u);
                ldsm4(bl[np], BbL + (uint32_t)np * 2304u + ks * 32u);
            }
#pragma unroll
            for (int nt = 0; nt < 4; nt++) {
                uint32_t b0h = bh[nt >> 1][(nt & 1) * 2];
                uint32_t b1h = bh[nt >> 1][(nt & 1) * 2 + 1];
                uint32_t b0l = bl[nt >> 1][(nt & 1) * 2];
                uint32_t b1l = bl[nt >> 1][(nt & 1) * 2 + 1];
                mma_bf16(acc[0][nt], ah0, b0h, b1h);   // AH*BH
                mma_bf16(acc[1][nt], ah1, b0h, b1h);
                mma_bf16(acc[0][nt], ah0, b0l, b1l);   // AH*BL
                mma_bf16(acc[1][nt], ah1, b0l, b1l);
                mma_bf16(acc[0][nt], al0, b0h, b1h);   // AL*BH
                mma_bf16(acc[1][nt], al1, b0h, b1h);
            }
        }
        __syncthreads();
    }

#pragma unroll
    for (int ms = 0; ms < 2; ms++) {
        int rA = r0 + warpM + ms * 16 + (lane >> 2);
        int rB = rA + 8;
#pragma unroll
        for (int nt = 0; nt < 4; nt++) {
            int col = warpN + nt * 8 + (lane & 3) * 2;
            if (rA < ROWS)
                *(float2*)&out[((size_t)z * BDIM * ROWS + (size_t)b * ROWS + rA)
                               * HDIM + col] =
                    make_float2(acc[ms][nt][0], acc[ms][nt][1]);
            if (rB < ROWS)
                *(float2*)&out[((size_t)z * BDIM * ROWS + (size_t)b * ROWS + rB)
                               * HDIM + col] =
                    make_float2(acc[ms][nt][2], acc[ms][nt][3]);
        }
    }
}

// ---------------------------------------------------------------------------
// Tensor-core econv, fp16 SINGLE-TERM A (A = emb rounded fp16, 1 plane),
// 256 threads / 8 warps, warp tile 32x64. B = EN fp16 (cp.async dbl-buf).
// Per warp-ks: 2 A-ldsm + 4 B-ldsm + 16 mma (halved vs r14).
// A-build fuses the split-K reduce of g_embp.
// ---------------------------------------------------------------------------
#define ASTRB 272u
#define PLANE 34816u
#define OFF_AH 0u
#define OFF_B  34816u                // stage s at OFF_B + s*34816 (single plane)
#define OFF_EV 104448u               // float [NH_PER][128]
#define SM_ECONV 120832u

__global__ void __launch_bounds__(256) k_econv_tc(const float* __restrict__ ev,
                                                  const unsigned short* __restrict__ ENfp,
                                                  float* __restrict__ newp) {
    extern __shared__ char smraw[];
    uint32_t base32 = smem_u32(smraw);
    float* evs = (float*)(smraw + OFF_EV);

    int t = threadIdx.x;
    int lane = t & 31, w = t >> 5;
    int r0 = blockIdx.x * 128;
    int hbase = blockIdx.y * NH_PER;

    // ---- issue stage-0 B copy immediately (overlaps A build) ----
    {
        const char* sB = (const char*)(ENfp + (size_t)hbase * 16384);
        uint32_t dst = base32 + OFF_B;
#pragma unroll
        for (int k = 0; k < 8; k++) {
            int f = t + 256 * k;
            uint32_t i = (uint32_t)(f >> 4), seg = (uint32_t)(f & 15);
            cp16(dst + i * ASTRB + seg * 16u, sB + (size_t)f * 16);
        }
        cp_commit();
    }

    // ---- build A plane: emb = sum_z embp[z], rounded fp16 ----
#pragma unroll 4
    for (int k = 0; k < 32; k++) {
        int p = t + 256 * k;
        int m = p >> 6, jp = p & 63;
        int r = r0 + m;
        float ex = 0.f, ey = 0.f;
        if (r < RTOT) {
#pragma unroll
            for (int z = 0; z < ZN2E; z++) {
                float2 v = *(const float2*)&g_embp[((size_t)z * RTOT + r) * HDIM
                                                   + jp * 2];
                ex += v.x; ey += v.y;
            }
        }
        __half2 hp = __halves2half2(__float2half_rn(ex), __float2half_rn(ey));
        *(uint32_t*)(smraw + OFF_AH + (uint32_t)m * ASTRB + jp * 4)
            = *(uint32_t*)&hp;
    }
    // ---- stage ev slice ----
    for (int idx = t; idx < NH_PER * 128; idx += 256) {
        int hh = idx >> 7, m = idx & 127;
        int r = r0 + m;
        evs[hh * 128 + m] = (r < RTOT) ? ev[(size_t)r * HDIM + hbase + hh] : 0.f;
    }

    float acc[2][8][4];
#pragma unroll
    for (int ms = 0; ms < 2; ms++)
#pragma unroll
        for (int nt = 0; nt < 8; nt++)
#pragma unroll
            for (int q = 0; q < 4; q++) acc[ms][nt][q] = 0.f;

    int warpM = (w & 3) * 32;
    int warpN = (w >> 2) * 64;
    uint32_t aoff = (uint32_t)(warpM + (lane & 15)) * ASTRB + (uint32_t)(lane >> 4) * 16u;
    uint32_t boff = (uint32_t)(warpN + ((lane >> 4) & 1) * 8 + (lane & 7)) * ASTRB
                  + (uint32_t)((lane >> 3) & 1) * 16u;
    uint32_t AbH = base32 + OFF_AH + aoff;

    int rl0 = warpM + (lane >> 2);

    for (int hh = 0; hh < NH_PER; hh++) {
        int s = hh & 1;
        cp_wait0();
        __syncthreads();                 // stage-s B visible; readers of 1-s done
                                         // (also covers A-plane/evs at hh=0)
        if (hh + 1 < NH_PER) {
            const char* sB = (const char*)(ENfp + (size_t)(hbase + hh + 1) * 16384);
            uint32_t dst = base32 + OFF_B + (uint32_t)(1 - s) * PLANE;
#pragma unroll
            for (int k = 0; k < 8; k++) {
                int f = t + 256 * k;
                uint32_t i = (uint32_t)(f >> 4), seg = (uint32_t)(f & 15);
                cp16(dst + i * ASTRB + seg * 16u, sB + (size_t)f * 16);
            }
            cp_commit();
        }

        uint32_t Bb = base32 + OFF_B + (uint32_t)s * PLANE + boff;

        float tt[2][8][4];
#pragma unroll
        for (int ms = 0; ms < 2; ms++)
#pragma unroll
            for (int nt = 0; nt < 8; nt++)
#pragma unroll
                for (int q = 0; q < 4; q++) tt[ms][nt][q] = 0.f;

#pragma unroll
        for (int ks = 0; ks < 8; ks++) {
            uint32_t ah0[4], ah1[4];
            ldsm4(ah0, AbH + ks * 32u);
            ldsm4(ah1, AbH + 4352u + ks * 32u);
            uint32_t bh[4][4];
#pragma unroll
            for (int np = 0; np < 4; np++)
                ldsm4(bh[np], Bb + (uint32_t)np * 4352u + ks * 32u);
#pragma unroll
            for (int nt = 0; nt < 8; nt++) {
                uint32_t b0 = bh[nt >> 1][(nt & 1) * 2];
                uint32_t b1 = bh[nt >> 1][(nt & 1) * 2 + 1];
                mma_f16(tt[0][nt], ah0, b0, b1);
                mma_f16(tt[1][nt], ah1, b0, b1);
            }
        }

        const float* evh = evs + hh * 128;
        float ev0A = evh[rl0];
        float ev0B = evh[rl0 + 8];
        float ev1A = evh[rl0 + 16];
        float ev1B = evh[rl0 + 24];
#pragma unroll
        for (int nt = 0; nt < 8; nt++) {
            acc[0][nt][0] += ev0A * tt[0][nt][0];
            acc[0][nt][1] += ev0A * tt[0][nt][1];
            acc[0][nt][2] += ev0B * tt[0][nt][2];
            acc[0][nt][3] += ev0B * tt[0][nt][3];
            acc[1][nt][0] += ev1A * tt[1][nt][0];
            acc[1][nt][1] += ev1A * tt[1][nt][1];
            acc[1][nt][2] += ev1B * tt[1][nt][2];
            acc[1][nt][3] += ev1B * tt[1][nt][3];
        }
    }

    size_t obase = (size_t)blockIdx.y * RTOT * HDIM;
#pragma unroll
    for (int ms = 0; ms < 2; ms++) {
        int rA = r0 + warpM + ms * 16 + (lane >> 2);
        int rB = rA + 8;
#pragma unroll
        for (int nt = 0; nt < 8; nt++) {
            int col = warpN + nt * 8 + (lane & 3) * 2;
            if (rA < RTOT)
                *(float2*)&newp[obase + (size_t)rA * HDIM + col] =
                    make_float2(acc[ms][nt][0], acc[ms][nt][1]);
            if (rB < RTOT)
                *(float2*)&newp[obase + (size_t)rB * HDIM + col] =
                    make_float2(acc[ms][nt][2], acc[ms][nt][3]);
        }
    }
}

// out = (sum_z g_aggp[z] + node_state) * g_inv    (grid 250 exact)
__global__ void __launch_bounds__(256) k_fin(const float* __restrict__ ns,
                                             float* __restrict__ out) {
    const size_t STR = (size_t)BDIM * NDIM * HDIM / 4;
    size_t f = (size_t)blockIdx.x * 256 + threadIdx.x;
    const float4* p = (const float4*)g_aggp;
    float4 s = p[f];
#pragma unroll
    for (int z = 1; z < ZAGG; z++) {
        float4 v = p[z * STR + f];
        s.x += v.x; s.y += v.y; s.z += v.z; s.w += v.w;
    }
    float4 n4 = ((const float4*)ns)[f];
    float inv = g_inv[(f * 4) >> 7];
    float4 o;
    o.x = (s.x + n4.x) * inv;
    o.y = (s.y + n4.y) * inv;
    o.z = (s.z + n4.z) * inv;
    o.w = (s.w + n4.w) * inv;
    ((float4*)out)[f] = o;
}

// ---------------------------------------------------------------------------
extern "C" void kernel_launch(void* const* d_in, const int* in_sizes, int n_in,
                              void* d_out, int out_size) {
    const float* node_state   = (const float*)d_in[0];
    const float* edge_vec     = (const float*)d_in[1];
    const float* node2edge    = (const float*)d_in[2];
    const float* edge2node    = (const float*)d_in[3];
    const float* edge_network = (const float*)d_in[4];
    float* out = (float*)d_out;

    void* p_embp; cudaGetSymbolAddress(&p_embp, g_embp);
    void* p_newp; cudaGetSymbolAddress(&p_newp, g_newp);
    void* p_aggp; cudaGetSymbolAddress(&p_aggp, g_aggp);
    void* p_n2eH; cudaGetSymbolAddress(&p_n2eH, g_n2eH);
    void* p_n2eL; cudaGetSymbolAddress(&p_n2eL, g_n2eL);
    void* p_e2nH; cudaGetSymbolAddress(&p_e2nH, g_e2nH);
    void* p_e2nL; cudaGetSymbolAddress(&p_e2nL, g_e2nL);
    void* p_nsTH; cudaGetSymbolAddress(&p_nsTH, g_nsTH);
    void* p_nsTL; cudaGetSymbolAddress(&p_nsTL, g_nsTL);
    void* p_nwTH; cudaGetSymbolAddress(&p_nwTH, g_nwTH);
    void* p_nwTL; cudaGetSymbolAddress(&p_nwTL, g_nwTL);
    void* p_enf;  cudaGetSymbolAddress(&p_enf,  g_ENfp);

    cudaFuncSetAttribute(k_econv_tc, cudaFuncAttributeMaxDynamicSharedMemorySize,
                         SM_ECONV);
    cudaFuncSetAttribute(k_gemm_tc2, cudaFuncAttributeMaxDynamicSharedMemorySize,
                         SM_GEMM2);

    // fused prologue: EN prep + both row splits (+norm) + node_state transpose
    k_pre<<<SEC3, 256>>>(edge_network, node2edge, edge2node, node_state);
    // n2e: (16,2,4) = 128 blocks
    k_gemm_tc2<<<dim3(16, BDIM, ZN2E), 512, SM_GEMM2>>>(
        (const unsigned short*)p_n2eH, (const unsigned short*)p_n2eL,
        (const unsigned short*)p_nsTH, (const unsigned short*)p_nsTL,
        (float*)p_embp, EDIM, KP1);
    // econv (fp16 single-term A, 8 warps x 32x64 tiles)
    k_econv_tc<<<dim3(32, HSPLIT), 256, SM_ECONV>>>(edge_vec,
                                                    (const unsigned short*)p_enf,
                                                    (float*)p_newp);
    // HSPLIT-reduce + transpose + split -> g_nwT planes
    k_nredT<<<dim3(64, 4, BDIM), 256>>>((const float*)p_newp);
    // agg: (8,2,8) = 128 blocks
    k_gemm_tc2<<<dim3(8, BDIM, ZAGG), 512, SM_GEMM2>>>(
        (const unsigned short*)p_e2nH, (const unsigned short*)p_e2nL,
        (const unsigned short*)p_nwTH, (const unsigned short*)p_nwTL,
        (float*)p_aggp, NDIM, KP2);
    k_fin<<<250, 256>>>(node_state, out);
}

// round 16
// speedup vs baseline: 2.9006x; 1.1707x over previous
#include <cuda_runtime.h>
#include <cuda_bf16.h>
#include <cuda_fp16.h>
#include <cstdint>

#define BDIM 2
#define NDIM 1000
#define EDIM 2000
#define HDIM 128
#define RTOT (BDIM * EDIM)          // 4000 flat rows

#define HSPLIT 4                    // h-splits for econv tensor kernel
#define NH_PER (HDIM / HSPLIT)      // 32 h per block

#define ZN2E 4                      // split-K for n2e tc-gemm (KP=1024 -> 256)
#define ZAGG 8                      // split-K for agg tc-gemm (KP=2048 -> 256)
#define KP1  1024                   // node2edge K=1000 padded
#define KP2  2048                   // edge2node K=2000 padded

// ---------------- scratch (device globals) ---------------------------------
__device__ float g_embp[(size_t)ZN2E * RTOT * HDIM];          // n2e partials
__device__ float g_newp[(size_t)HSPLIT * RTOT * HDIM];        // econv partials
__device__ float g_aggp[(size_t)ZAGG * BDIM * NDIM * HDIM];   // agg partials
__device__ float g_inv [(size_t)BDIM * NDIM];
// fp16 operand planes (pre-converted, K-padded) for glue GEMMs
__device__ unsigned short g_n2eF[(size_t)RTOT * KP1];
__device__ unsigned short g_e2nF[(size_t)BDIM * NDIM * KP2];
__device__ unsigned short g_nsTF[(size_t)BDIM * HDIM * KP1];
__device__ unsigned short g_nwTF[(size_t)BDIM * HDIM * KP2];
// EN as single fp16 plane, plain [h][i][j] layout (econv B operand)
__device__ unsigned short g_ENfp[(size_t)HDIM * 16384];

// ---------------- helpers ---------------------------------------------------
__device__ __forceinline__ uint32_t smem_u32(const void* p) {
    uint32_t a;
    asm("{ .reg .u64 t; cvta.to.shared.u64 t, %1; cvt.u32.u64 %0, t; }"
        : "=r"(a) : "l"(p));
    return a;
}
__device__ __forceinline__ void ldsm4(uint32_t* r, uint32_t addr) {
    asm volatile("ldmatrix.sync.aligned.m8n8.x4.shared.b16 {%0,%1,%2,%3}, [%4];"
                 : "=r"(r[0]), "=r"(r[1]), "=r"(r[2]), "=r"(r[3]) : "r"(addr));
}
__device__ __forceinline__ void mma_f16(float* d, const uint32_t* a,
                                        uint32_t b0, uint32_t b1) {
    asm volatile("mma.sync.aligned.m16n8k16.row.col.f32.f16.f16.f32 "
                 "{%0,%1,%2,%3}, {%4,%5,%6,%7}, {%8,%9}, {%0,%1,%2,%3};"
                 : "+f"(d[0]), "+f"(d[1]), "+f"(d[2]), "+f"(d[3])
                 : "r"(a[0]), "r"(a[1]), "r"(a[2]), "r"(a[3]), "r"(b0), "r"(b1));
}
__device__ __forceinline__ void cp16(uint32_t dst, const void* src) {
    asm volatile("cp.async.cg.shared.global [%0], [%1], 16;"
                 :: "r"(dst), "l"(src) : "memory");
}
__device__ __forceinline__ void cp_commit() {
    asm volatile("cp.async.commit_group;" ::: "memory");
}
__device__ __forceinline__ void cp_wait0() {
    asm volatile("cp.async.wait_group 0;" ::: "memory");
}
__device__ __forceinline__ unsigned short f2h(float v) {
    __half hv = __float2half_rn(v);
    return *(unsigned short*)&hv;
}

// ---------------------------------------------------------------------------
// Fused prologue kernel: grid sections dispatch the 4 independent prep tasks
//   [0,128)                : EN -> fp16 plane
//   [128, 128+RTOT)        : node2edge -> fp16, KP1
//   [.., +BDIM*NDIM)       : edge2node -> fp16, KP2  (+ rowsum -> g_inv)
//   [.., +256)             : node_state -> transposed fp16, KP1
// ---------------------------------------------------------------------------
#define SEC0 128
#define SEC1 (SEC0 + RTOT)
#define SEC2 (SEC1 + BDIM * NDIM)
#define SEC3 (SEC2 + 256)

__global__ void __launch_bounds__(256) k_pre(const float* __restrict__ EN,
                                             const float* __restrict__ n2e,
                                             const float* __restrict__ e2n,
                                             const float* __restrict__ ns) {
    int bid = blockIdx.x;
    int t = threadIdx.x;

    if (bid < SEC0) {                        // EN -> fp16
        int h = bid;
        const float* src = EN + (size_t)h * 16384;
        unsigned short* dp = g_ENfp + (size_t)h * 16384;
        for (int idx = t; idx < 16384; idx += 256)
            dp[idx] = f2h(src[idx]);
        return;
    }
    if (bid < SEC2) {                        // row-wise fp16 converts
        int is2 = (bid >= SEC1);
        int row = bid - (is2 ? SEC1 : SEC0);
        int K    = is2 ? EDIM : NDIM;
        int KPAD = is2 ? KP2 : KP1;
        const float* src = (is2 ? e2n : n2e) + (size_t)row * K;
        unsigned short* dp = (is2 ? g_e2nF : g_n2eF) + (size_t)row * KPAD;
        __shared__ float red[256];
        float sum = 0.f;
        for (int idx = t; idx < KPAD; idx += 256) {
            float v = (idx < K) ? src[idx] : 0.f;
            sum += v;
            dp[idx] = f2h(v);
        }
        if (is2) {
            red[t] = sum;
            __syncthreads();
            for (int o = 128; o > 0; o >>= 1) {
                if (t < o) red[t] += red[t + o];
                __syncthreads();
            }
            if (t == 0) g_inv[row] = 1.f / (1.f + red[0]);
        }
        return;
    }
    {                                        // node_state transpose + fp16
        int idx = bid - SEC2;                // 0..255  (32 x 4 x BDIM)
        int xb = idx & 31, yb = (idx >> 5) & 3, b = idx >> 7;
        __shared__ float tile[32][33];
        int n0 = xb * 32, h0 = yb * 32;
        int tx = t & 31, ty = t >> 5;
        for (int rr = ty; rr < 32; rr += 8) {
            int n = n0 + rr;
            tile[rr][tx] = (n < NDIM)
                ? ns[((size_t)b * NDIM + n) * HDIM + h0 + tx] : 0.f;
        }
        __syncthreads();
        for (int cc = ty; cc < 32; cc += 8) {
            int h = h0 + cc, n = n0 + tx;    // n < 1024 = KP1 always
            g_nsTF[((size_t)b * HDIM + h) * KP1 + n] = f2h(tile[tx][cc]);
        }
    }
}

// ---------------------------------------------------------------------------
// HSPLIT-reduce + transpose + fp16: g_nwTF[b][i][KP2] from newp partials
// grid (64, 4, BDIM) -> e tiles cover 2048 = KP2 (zero-padded past EDIM)
// ---------------------------------------------------------------------------
__global__ void __launch_bounds__(256) k_nredT(const float* __restrict__ newp) {
    __shared__ float tile[32][33];
    int b  = blockIdx.z;
    int e0 = blockIdx.x * 32, i0 = blockIdx.y * 32;
    int tx = threadIdx.x & 31, ty = threadIdx.x >> 5;
    for (int rr = ty; rr < 32; rr += 8) {
        int e = e0 + rr;
        float s = 0.f;
        if (e < EDIM) {
            size_t base = ((size_t)b * EDIM + e) * HDIM + i0 + tx;
#pragma unroll
            for (int z = 0; z < HSPLIT; z++)
                s += newp[(size_t)z * RTOT * HDIM + base];
        }
        tile[rr][tx] = s;
    }
    __syncthreads();
    for (int cc = ty; cc < 32; cc += 8) {
        int i = i0 + cc, e = e0 + tx;           // e < 2048 = KP2 always
        g_nwTF[((size_t)b * HDIM + i) * KP2 + e] = f2h(tile[tx][cc]);
    }
}

// ---------------------------------------------------------------------------
// Tensor-core split-K GEMM on single-fp16 planes:
//   out[z][b][r][i] = sum_{k in z-chunk of 256} A[b][r][k] * BT[b][i][k]
// 512 threads, 16 warps, warp tile 32x32; cp.async double-buffered over kc.
// 2 planes/stage (A, B); 1 mma term.
// ---------------------------------------------------------------------------
#define TSTR 144u                   // (64 fp16 = 128B) + 16B pad
#define PL2  18432u                 // plane: 128*144
#define STGF 36864u                 // stage: 2 planes (A, B)
#define SM_GEMMF 73728u             // 2 stages

__global__ void __launch_bounds__(512) k_gemm_f16(const unsigned short* __restrict__ A,
                                                  const unsigned short* __restrict__ BT,
                                                  float* __restrict__ out,
                                                  int ROWS, int KPAD) {
    extern __shared__ char smraw[];
    uint32_t base32 = smem_u32(smraw);

    int t = threadIdx.x;
    int lane = t & 31, w = t >> 5;
    int b  = blockIdx.y;
    int z  = blockIdx.z;
    int r0 = blockIdx.x * 128;

    auto copy_kc = [&](int kc, int s) {
        int k0 = z * 256 + kc * 64;
#pragma unroll
        for (int q = 0; q < 4; q++) {
            int f = t + 512 * q;            // 0..2047
            int pl = f >> 10;
            int idx = f & 1023;
            int row = idx >> 3, seg = idx & 7;
            uint32_t dst = base32 + (uint32_t)s * STGF + (uint32_t)pl * PL2
                         + (uint32_t)row * TSTR + (uint32_t)seg * 16u;
            if (pl == 0) {                  // A plane: guard ragged M
                int rg = r0 + row;
                if (rg < ROWS) {
                    cp16(dst, A + ((size_t)b * ROWS + rg) * KPAD + k0 + seg * 8);
                } else {
                    *(uint4*)(smraw + (uint32_t)s * STGF
                              + (uint32_t)row * TSTR + (uint32_t)seg * 16u)
                        = make_uint4(0, 0, 0, 0);
                }
            } else {                        // B plane: 128 rows exact
                cp16(dst, BT + ((size_t)b * HDIM + row) * KPAD + k0 + seg * 8);
            }
        }
        cp_commit();
    };

    float acc[2][4][4];
#pragma unroll
    for (int ms = 0; ms < 2; ms++)
#pragma unroll
        for (int nt = 0; nt < 4; nt++)
#pragma unroll
            for (int q = 0; q < 4; q++) acc[ms][nt][q] = 0.f;

    int warpM = (w & 3) * 32;
    int warpN = (w >> 2) * 32;
    uint32_t aoff = (uint32_t)(warpM + (lane & 15)) * TSTR + (uint32_t)(lane >> 4) * 16u;
    uint32_t boff = (uint32_t)(warpN + ((lane >> 4) & 1) * 8 + (lane & 7)) * TSTR
                  + (uint32_t)((lane >> 3) & 1) * 16u;

    copy_kc(0, 0);                          // prologue

    for (int kc = 0; kc < 4; kc++) {
        int s = kc & 1;
        cp_wait0();
        __syncthreads();
        if (kc + 1 < 4) copy_kc(kc + 1, 1 - s);

        uint32_t Ab = base32 + (uint32_t)s * STGF + aoff;
        uint32_t Bb = base32 + (uint32_t)s * STGF + PL2 + boff;

#pragma unroll
        for (int ks = 0; ks < 4; ks++) {
            uint32_t a0[4], a1[4];
            ldsm4(a0, Ab + ks * 32u);
            ldsm4(a1, Ab + 2304u + ks * 32u);        // +16 rows
            uint32_t bh[2][4];
#pragma unroll
            for (int np = 0; np < 2; np++)
                ldsm4(bh[np], Bb + (uint32_t)np * 2304u + ks * 32u);
#pragma unroll
            for (int nt = 0; nt < 4; nt++) {
                uint32_t b0 = bh[nt >> 1][(nt & 1) * 2];
                uint32_t b1 = bh[nt >> 1][(nt & 1) * 2 + 1];
                mma_f16(acc[0][nt], a0, b0, b1);
                mma_f16(acc[1][nt], a1, b0, b1);
            }
        }
        __syncthreads();
    }

#pragma unroll
    for (int ms = 0; ms < 2; ms++) {
        int rA = r0 + warpM + ms * 16 + (lane >> 2);
        int rB = rA + 8;
#pragma unroll
        for (int nt = 0; nt < 4; nt++) {
            int col = warpN + nt * 8 + (lane & 3) * 2;
            if (rA < ROWS)
                *(float2*)&out[((size_t)z * BDIM * ROWS + (size_t)b * ROWS + rA)
                               * HDIM + col] =
                    make_float2(acc[ms][nt][0], acc[ms][nt][1]);
            if (rB < ROWS)
                *(float2*)&out[((size_t)z * BDIM * ROWS + (size_t)b * ROWS + rB)
                               * HDIM + col] =
                    make_float2(acc[ms][nt][2], acc[ms][nt][3]);
        }
    }
}

// ---------------------------------------------------------------------------
// Tensor-core econv (r15-proven, unchanged): fp16 single-term A, 256 threads,
// 8 warps x 32x64 tiles; B = EN fp16 cp.async double-buffered; A-build fuses
// the split-K reduce of g_embp.
// ---------------------------------------------------------------------------
#define ASTRB 272u
#define PLANE 34816u
#define OFF_AH 0u
#define OFF_B  34816u
#define OFF_EV 104448u
#define SM_ECONV 120832u

__global__ void __launch_bounds__(256) k_econv_tc(const float* __restrict__ ev,
                                                  const unsigned short* __restrict__ ENfp,
                                                  float* __restrict__ newp) {
    extern __shared__ char smraw[];
    uint32_t base32 = smem_u32(smraw);
    float* evs = (float*)(smraw + OFF_EV);

    int t = threadIdx.x;
    int lane = t & 31, w = t >> 5;
    int r0 = blockIdx.x * 128;
    int hbase = blockIdx.y * NH_PER;

    {
        const char* sB = (const char*)(ENfp + (size_t)hbase * 16384);
        uint32_t dst = base32 + OFF_B;
#pragma unroll
        for (int k = 0; k < 8; k++) {
            int f = t + 256 * k;
            uint32_t i = (uint32_t)(f >> 4), seg = (uint32_t)(f & 15);
            cp16(dst + i * ASTRB + seg * 16u, sB + (size_t)f * 16);
        }
        cp_commit();
    }

#pragma unroll 4
    for (int k = 0; k < 32; k++) {
        int p = t + 256 * k;
        int m = p >> 6, jp = p & 63;
        int r = r0 + m;
        float ex = 0.f, ey = 0.f;
        if (r < RTOT) {
#pragma unroll
            for (int z = 0; z < ZN2E; z++) {
                float2 v = *(const float2*)&g_embp[((size_t)z * RTOT + r) * HDIM
                                                   + jp * 2];
                ex += v.x; ey += v.y;
            }
        }
        __half2 hp = __halves2half2(__float2half_rn(ex), __float2half_rn(ey));
        *(uint32_t*)(smraw + OFF_AH + (uint32_t)m * ASTRB + jp * 4)
            = *(uint32_t*)&hp;
    }
    for (int idx = t; idx < NH_PER * 128; idx += 256) {
        int hh = idx >> 7, m = idx & 127;
        int r = r0 + m;
        evs[hh * 128 + m] = (r < RTOT) ? ev[(size_t)r * HDIM + hbase + hh] : 0.f;
    }

    float acc[2][8][4];
#pragma unroll
    for (int ms = 0; ms < 2; ms++)
#pragma unroll
        for (int nt = 0; nt < 8; nt++)
#pragma unroll
            for (int q = 0; q < 4; q++) acc[ms][nt][q] = 0.f;

    int warpM = (w & 3) * 32;
    int warpN = (w >> 2) * 64;
    uint32_t aoff = (uint32_t)(warpM + (lane & 15)) * ASTRB + (uint32_t)(lane >> 4) * 16u;
    uint32_t boff = (uint32_t)(warpN + ((lane >> 4) & 1) * 8 + (lane & 7)) * ASTRB
                  + (uint32_t)((lane >> 3) & 1) * 16u;
    uint32_t AbH = base32 + OFF_AH + aoff;

    int rl0 = warpM + (lane >> 2);

    for (int hh = 0; hh < NH_PER; hh++) {
        int s = hh & 1;
        cp_wait0();
        __syncthreads();

        if (hh + 1 < NH_PER) {
            const char* sB = (const char*)(ENfp + (size_t)(hbase + hh + 1) * 16384);
            uint32_t dst = base32 + OFF_B + (uint32_t)(1 - s) * PLANE;
#pragma unroll
            for (int k = 0; k < 8; k++) {
                int f = t + 256 * k;
                uint32_t i = (uint32_t)(f >> 4), seg = (uint32_t)(f & 15);
                cp16(dst + i * ASTRB + seg * 16u, sB + (size_t)f * 16);
            }
            cp_commit();
        }

        uint32_t Bb = base32 + OFF_B + (uint32_t)s * PLANE + boff;

        float tt[2][8][4];
#pragma unroll
        for (int ms = 0; ms < 2; ms++)
#pragma unroll
            for (int nt = 0; nt < 8; nt++)
#pragma unroll
                for (int q = 0; q < 4; q++) tt[ms][nt][q] = 0.f;

#pragma unroll
        for (int ks = 0; ks < 8; ks++) {
            uint32_t ah0[4], ah1[4];
            ldsm4(ah0, AbH + ks * 32u);
            ldsm4(ah1, AbH + 4352u + ks * 32u);
            uint32_t bh[4][4];
#pragma unroll
            for (int np = 0; np < 4; np++)
                ldsm4(bh[np], Bb + (uint32_t)np * 4352u + ks * 32u);
#pragma unroll
            for (int nt = 0; nt < 8; nt++) {
                uint32_t b0 = bh[nt >> 1][(nt & 1) * 2];
                uint32_t b1 = bh[nt >> 1][(nt & 1) * 2 + 1];
                mma_f16(tt[0][nt], ah0, b0, b1);
                mma_f16(tt[1][nt], ah1, b0, b1);
            }
        }

        const float* evh = evs + hh * 128;
        float ev0A = evh[rl0];
        float ev0B = evh[rl0 + 8];
        float ev1A = evh[rl0 + 16];
        float ev1B = evh[rl0 + 24];
#pragma unroll
        for (int nt = 0; nt < 8; nt++) {
            acc[0][nt][0] += ev0A * tt[0][nt][0];
            acc[0][nt][1] += ev0A * tt[0][nt][1];
            acc[0][nt][2] += ev0B * tt[0][nt][2];
            acc[0][nt][3] += ev0B * tt[0][nt][3];
            acc[1][nt][0] += ev1A * tt[1][nt][0];
            acc[1][nt][1] += ev1A * tt[1][nt][1];
            acc[1][nt][2] += ev1B * tt[1][nt][2];
            acc[1][nt][3] += ev1B * tt[1][nt][3];
        }
    }

    size_t obase = (size_t)blockIdx.y * RTOT * HDIM;
#pragma unroll
    for (int ms = 0; ms < 2; ms++) {
        int rA = r0 + warpM + ms * 16 + (lane >> 2);
        int rB = rA + 8;
#pragma unroll
        for (int nt = 0; nt < 8; nt++) {
            int col = warpN + nt * 8 + (lane & 3) * 2;
            if (rA < RTOT)
                *(float2*)&newp[obase + (size_t)rA * HDIM + col] =
                    make_float2(acc[ms][nt][0], acc[ms][nt][1]);
            if (rB < RTOT)
                *(float2*)&newp[obase + (size_t)rB * HDIM + col] =
                    make_float2(acc[ms][nt][2], acc[ms][nt][3]);
        }
    }
}

// out = (sum_z g_aggp[z] + node_state) * g_inv    (grid 250 exact)
__global__ void __launch_bounds__(256) k_fin(const float* __restrict__ ns,
                                             float* __restrict__ out) {
    const size_t STR = (size_t)BDIM * NDIM * HDIM / 4;
    size_t f = (size_t)blockIdx.x * 256 + threadIdx.x;
    const float4* p = (const float4*)g_aggp;
    float4 s = p[f];
#pragma unroll
    for (int z = 1; z < ZAGG; z++) {
        float4 v = p[z * STR + f];
        s.x += v.x; s.y += v.y; s.z += v.z; s.w += v.w;
    }
    float4 n4 = ((const float4*)ns)[f];
    float inv = g_inv[(f * 4) >> 7];
    float4 o;
    o.x = (s.x + n4.x) * inv;
    o.y = (s.y + n4.y) * inv;
    o.z = (s.z + n4.z) * inv;
    o.w = (s.w + n4.w) * inv;
    ((float4*)out)[f] = o;
}

// ---------------------------------------------------------------------------
extern "C" void kernel_launch(void* const* d_in, const int* in_sizes, int n_in,
                              void* d_out, int out_size) {
    const float* node_state   = (const float*)d_in[0];
    const float* edge_vec     = (const float*)d_in[1];
    const float* node2edge    = (const float*)d_in[2];
    const float* edge2node    = (const float*)d_in[3];
    const float* edge_network = (const float*)d_in[4];
    float* out = (float*)d_out;

    void* p_embp; cudaGetSymbolAddress(&p_embp, g_embp);
    void* p_newp; cudaGetSymbolAddress(&p_newp, g_newp);
    void* p_aggp; cudaGetSymbolAddress(&p_aggp, g_aggp);
    void* p_n2eF; cudaGetSymbolAddress(&p_n2eF, g_n2eF);
    void* p_e2nF; cudaGetSymbolAddress(&p_e2nF, g_e2nF);
    void* p_nsTF; cudaGetSymbolAddress(&p_nsTF, g_nsTF);
    void* p_nwTF; cudaGetSymbolAddress(&p_nwTF, g_nwTF);
    void* p_enf;  cudaGetSymbolAddress(&p_enf,  g_ENfp);

    cudaFuncSetAttribute(k_econv_tc, cudaFuncAttributeMaxDynamicSharedMemorySize,
                         SM_ECONV);
    cudaFuncSetAttribute(k_gemm_f16, cudaFuncAttributeMaxDynamicSharedMemorySize,
                         SM_GEMMF);

    // fused prologue: EN prep + both row converts (+norm) + node_state transpose
    k_pre<<<SEC3, 256>>>(edge_network, node2edge, edge2node, node_state);
    // n2e: (16,2,4) = 128 blocks
    k_gemm_f16<<<dim3(16, BDIM, ZN2E), 512, SM_GEMMF>>>(
        (const unsigned short*)p_n2eF, (const unsigned short*)p_nsTF,
        (float*)p_embp, EDIM, KP1);
    // econv (fp16 single-term A, 8 warps x 32x64 tiles)
    k_econv_tc<<<dim3(32, HSPLIT), 256, SM_ECONV>>>(edge_vec,
                                                    (const unsigned short*)p_enf,
                                                    (float*)p_newp);
    // HSPLIT-reduce + transpose + fp16 -> g_nwTF
    k_nredT<<<dim3(64, 4, BDIM), 256>>>((const float*)p_newp);
    // agg: (8,2,8) = 128 blocks
    k_gemm_f16<<<dim3(8, BDIM, ZAGG), 512, SM_GEMMF>>>(
        (const unsigned short*)p_e2nF, (const unsigned short*)p_nwTF,
        (float*)p_aggp, NDIM, KP2);
    k_fin<<<250, 256>>>(node_state, out);
}